// round 1
// baseline (speedup 1.0000x reference)
#include <cuda_runtime.h>
#include <math.h>

// ---------------- model dims ----------------
#define BATCH 4
#define SEQL  1024
#define DMODEL 512
#define NHEAD 8
#define DK 64
#define NLAYERS 3
#define DFF 2048
#define INPUT_DIM 128
#define NUM_CLASSES 64
#define ROWS (BATCH*SEQL)        // 4096
#define TOPU 34                  // int(5*ln(1024)) = 34

// ---------------- scratch (static device globals; no allocations) ----------------
__device__ float g_h[ROWS*DMODEL];
__device__ float g_q[ROWS*DMODEL];
__device__ float g_k[ROWS*DMODEL];
__device__ float g_v[ROWS*DMODEL];
__device__ float g_attn[ROWS*DMODEL];
__device__ float g_tmp[ROWS*DFF];       // FF1 output (also big enough for proj tmp)
__device__ float g_tmp2[ROWS*DMODEL];   // proj / FF2 output before LN
__device__ float g_scores[(long long)BATCH*NHEAD*SEQL*SEQL];  // 134 MB

// ---------------- generic fp32 SGEMM: C = alpha*A@B(^T) (+bias) (+relu) ----------------
// 128x128 tile, BK=8, 256 threads, 8x8 microtile. Batched via blockIdx.z with
// (z/8, z%8) strides so Q/K/V head sub-matrices need no copies.
template<bool TRANSB, bool RELU, bool HASBIAS>
__global__ __launch_bounds__(256)
void gemm_kernel(const float* __restrict__ A, int lda, long long sAo, long long sAi,
                 const float* __restrict__ B, int ldb, long long sBo, long long sBi,
                 float* __restrict__ C, int ldc, long long sCo, long long sCi,
                 int M, int N, int K, const float* __restrict__ bias, float alpha)
{
    const int BM = 128, BN = 128, BK = 8;
    __shared__ float As[BK][BM];
    __shared__ float Bs[BK][BN];

    int z = blockIdx.z;
    A += (long long)(z >> 3) * sAo + (long long)(z & 7) * sAi;
    B += (long long)(z >> 3) * sBo + (long long)(z & 7) * sBi;
    C += (long long)(z >> 3) * sCo + (long long)(z & 7) * sCi;

    int bm = blockIdx.y * BM, bn = blockIdx.x * BN;
    int tid = threadIdx.x;
    int tx = tid & 15, ty = tid >> 4;

    float acc[8][8];
#pragma unroll
    for (int i = 0; i < 8; i++)
#pragma unroll
        for (int j = 0; j < 8; j++) acc[i][j] = 0.f;

    for (int k0 = 0; k0 < K; k0 += BK) {
        // A tile: BM x BK -> As[k][m]
#pragma unroll
        for (int i = 0; i < 4; i++) {
            int idx = tid * 4 + i;
            int m = idx >> 3, k = idx & 7;
            int gm = bm + m, gk = k0 + k;
            As[k][m] = (gm < M && gk < K) ? A[(long long)gm * lda + gk] : 0.f;
        }
        // B tile -> Bs[k][n]
#pragma unroll
        for (int i = 0; i < 4; i++) {
            int idx = tid * 4 + i;
            if (!TRANSB) {
                int k = idx >> 7, n = idx & 127;
                int gk = k0 + k, gn = bn + n;
                Bs[k][n] = (gk < K && gn < N) ? B[(long long)gk * ldb + gn] : 0.f;
            } else {
                int n = idx >> 3, k = idx & 7;
                int gn = bn + n, gk = k0 + k;
                Bs[k][n] = (gn < N && gk < K) ? B[(long long)gn * ldb + gk] : 0.f;
            }
        }
        __syncthreads();
#pragma unroll
        for (int k = 0; k < BK; k++) {
            float a[8], b[8];
#pragma unroll
            for (int i = 0; i < 8; i++) a[i] = As[k][ty * 8 + i];
#pragma unroll
            for (int j = 0; j < 8; j++) b[j] = Bs[k][tx * 8 + j];
#pragma unroll
            for (int i = 0; i < 8; i++)
#pragma unroll
                for (int j = 0; j < 8; j++) acc[i][j] += a[i] * b[j];
        }
        __syncthreads();
    }

#pragma unroll
    for (int i = 0; i < 8; i++) {
        int gm = bm + ty * 8 + i;
        if (gm >= M) continue;
#pragma unroll
        for (int j = 0; j < 8; j++) {
            int gn = bn + tx * 8 + j;
            if (gn >= N) continue;
            float vv = acc[i][j] * alpha;
            if (HASBIAS) vv += bias[gn];
            if (RELU) vv = fmaxf(vv, 0.f);
            C[(long long)gm * ldc + gn] = vv;
        }
    }
}

// ---------------- h = h*sqrt(D) + positional encoding ----------------
__global__ __launch_bounds__(256)
void pe_kernel(float* __restrict__ h)
{
    int row = blockIdx.x;            // 0..4095
    int pos = row & (SEQL - 1);      // row % 1024
    const float c = 0.01798894603901634f;   // ln(10000)/512
    const float scale = 22.62741699796952f; // sqrt(512)
#pragma unroll
    for (int it = 0; it < 2; it++) {
        int col = threadIdx.x + it * 256;
        int p2 = col & ~1;                        // 2*(col/2)
        float div = __expf(-(float)p2 * c);
        float arg = (float)pos * div;
        float pe = (col & 1) ? cosf(arg) : sinf(arg);
        long long idx = (long long)row * DMODEL + col;
        h[idx] = h[idx] * scale + pe;
    }
}

// ---------------- out = LayerNorm(resid + delta) * g + b ----------------
__global__ __launch_bounds__(256)
void add_ln_kernel(const float* __restrict__ resid, const float* __restrict__ delta,
                   float* __restrict__ out,
                   const float* __restrict__ g, const float* __restrict__ b)
{
    __shared__ float red[256];
    int row = blockIdx.x;
    int tid = threadIdx.x;
    long long base = (long long)row * DMODEL;
    float v0 = resid[base + tid]       + delta[base + tid];
    float v1 = resid[base + tid + 256] + delta[base + tid + 256];

    red[tid] = v0 + v1;
    __syncthreads();
    for (int s = 128; s > 0; s >>= 1) { if (tid < s) red[tid] += red[tid + s]; __syncthreads(); }
    float mean = red[0] * (1.f / DMODEL);
    __syncthreads();

    red[tid] = v0 * v0 + v1 * v1;
    __syncthreads();
    for (int s = 128; s > 0; s >>= 1) { if (tid < s) red[tid] += red[tid + s]; __syncthreads(); }
    float var = red[0] * (1.f / DMODEL) - mean * mean;
    float rstd = rsqrtf(var + 1e-5f);

    out[base + tid]       = (v0 - mean) * rstd * g[tid]       + b[tid];
    out[base + tid + 256] = (v1 - mean) * rstd * g[tid + 256] + b[tid + 256];
}

// ---------------- exact top-u threshold (radix select) + masked softmax ----------------
// One block per score row (32768 rows of 1024). Equivalent to the reference's
// where(s<kth,-1e4,s) + softmax because exp(-1e4 - m) == 0 in fp32.
__global__ __launch_bounds__(256)
void topk_softmax_kernel(float* __restrict__ scores)
{
    __shared__ int hist[256];
    __shared__ float red[256];
    __shared__ unsigned s_prefix;
    __shared__ int s_k;

    long long base = (long long)blockIdx.x * SEQL;
    int tid = threadIdx.x;

    float val[4];
    unsigned key[4];
#pragma unroll
    for (int i = 0; i < 4; i++) {
        val[i] = scores[base + tid + i * 256];
        unsigned bits = __float_as_uint(val[i]);
        key[i] = (bits & 0x80000000u) ? ~bits : (bits | 0x80000000u);
    }

    if (tid == 0) { s_prefix = 0u; s_k = TOPU; }
    __syncthreads();

    for (int shift = 24; shift >= 0; shift -= 8) {
        hist[tid] = 0;
        __syncthreads();
        unsigned pref = s_prefix;
#pragma unroll
        for (int i = 0; i < 4; i++) {
            bool active = (shift == 24) || ((key[i] >> (shift + 8)) == pref);
            if (active) atomicAdd(&hist[(key[i] >> shift) & 255u], 1);
        }
        __syncthreads();
        if (tid == 0) {
            int k = s_k, cum = 0, d = 255;
            for (; d >= 0; d--) { cum += hist[d]; if (cum >= k) break; }
            s_k = k - (cum - hist[d]);
            s_prefix = (pref << 8) | (unsigned)d;
        }
        __syncthreads();
    }

    unsigned tkey = s_prefix;
    unsigned tbits = (tkey & 0x80000000u) ? (tkey ^ 0x80000000u) : ~tkey;
    float thr = __uint_as_float(tbits);

    // masked softmax: keep val >= thr (same set as reference; ties kept)
    float m = -3.0e38f;
#pragma unroll
    for (int i = 0; i < 4; i++) if (val[i] >= thr) m = fmaxf(m, val[i]);
    red[tid] = m;
    __syncthreads();
    for (int s = 128; s > 0; s >>= 1) { if (tid < s) red[tid] = fmaxf(red[tid], red[tid + s]); __syncthreads(); }
    m = red[0];
    __syncthreads();

    float e[4]; float sum = 0.f;
#pragma unroll
    for (int i = 0; i < 4; i++) {
        e[i] = (val[i] >= thr) ? __expf(val[i] - m) : 0.f;
        sum += e[i];
    }
    red[tid] = sum;
    __syncthreads();
    for (int s = 128; s > 0; s >>= 1) { if (tid < s) red[tid] += red[tid + s]; __syncthreads(); }
    float inv = 1.f / red[0];
#pragma unroll
    for (int i = 0; i < 4; i++) scores[base + tid + i * 256] = e[i] * inv;
}

// ---------------- host launch ----------------
static inline dim3 gemm_grid(int M, int N, int Z) {
    return dim3((N + 127) / 128, (M + 127) / 128, Z);
}

extern "C" void kernel_launch(void* const* d_in, const int* in_sizes, int n_in,
                              void* d_out, int out_size)
{
    const float* x     = (const float*)d_in[0];
    const float* W_emb = (const float*)d_in[1];
    const float* b_emb = (const float*)d_in[2];
    const float* Wq    = (const float*)d_in[3];
    const float* bq    = (const float*)d_in[4];
    const float* Wk    = (const float*)d_in[5];
    const float* bk    = (const float*)d_in[6];
    const float* Wv    = (const float*)d_in[7];
    const float* bv    = (const float*)d_in[8];
    const float* Wo    = (const float*)d_in[9];
    const float* bo    = (const float*)d_in[10];
    const float* ln1_g = (const float*)d_in[11];
    const float* ln1_b = (const float*)d_in[12];
    const float* W1    = (const float*)d_in[13];
    const float* b1    = (const float*)d_in[14];
    const float* W2    = (const float*)d_in[15];
    const float* b2    = (const float*)d_in[16];
    const float* ln2_g = (const float*)d_in[17];
    const float* ln2_b = (const float*)d_in[18];
    const float* W_dec = (const float*)d_in[19];
    const float* b_dec = (const float*)d_in[20];
    float* out = (float*)d_out;

    float *h, *q, *k, *v, *attn, *tmp, *tmp2, *scores;
    cudaGetSymbolAddress((void**)&h,      g_h);
    cudaGetSymbolAddress((void**)&q,      g_q);
    cudaGetSymbolAddress((void**)&k,      g_k);
    cudaGetSymbolAddress((void**)&v,      g_v);
    cudaGetSymbolAddress((void**)&attn,   g_attn);
    cudaGetSymbolAddress((void**)&tmp,    g_tmp);
    cudaGetSymbolAddress((void**)&tmp2,   g_tmp2);
    cudaGetSymbolAddress((void**)&scores, g_scores);

    const long long HB = (long long)SEQL * DMODEL;          // per-batch row stride in Q/K/V
    const long long SB = (long long)SEQL * SEQL;            // per-(b,h) score matrix

    // h = (x @ W_emb + b_emb); then *= sqrt(D) and += PE
    gemm_kernel<false,false,true><<<gemm_grid(ROWS, DMODEL, 1), 256>>>(
        x, INPUT_DIM, 0, 0, W_emb, DMODEL, 0, 0, h, DMODEL, 0, 0,
        ROWS, DMODEL, INPUT_DIM, b_emb, 1.f);
    pe_kernel<<<ROWS, 256>>>(h);

    for (int l = 0; l < NLAYERS; l++) {
        const float* Wq_l = Wq + (long long)l * DMODEL * DMODEL;
        const float* Wk_l = Wk + (long long)l * DMODEL * DMODEL;
        const float* Wv_l = Wv + (long long)l * DMODEL * DMODEL;
        const float* Wo_l = Wo + (long long)l * DMODEL * DMODEL;
        const float* W1_l = W1 + (long long)l * DMODEL * DFF;
        const float* W2_l = W2 + (long long)l * DFF * DMODEL;

        gemm_kernel<false,false,true><<<gemm_grid(ROWS, DMODEL, 1), 256>>>(
            h, DMODEL, 0, 0, Wq_l, DMODEL, 0, 0, q, DMODEL, 0, 0,
            ROWS, DMODEL, DMODEL, bq + l * DMODEL, 1.f);
        gemm_kernel<false,false,true><<<gemm_grid(ROWS, DMODEL, 1), 256>>>(
            h, DMODEL, 0, 0, Wk_l, DMODEL, 0, 0, k, DMODEL, 0, 0,
            ROWS, DMODEL, DMODEL, bk + l * DMODEL, 1.f);
        gemm_kernel<false,false,true><<<gemm_grid(ROWS, DMODEL, 1), 256>>>(
            h, DMODEL, 0, 0, Wv_l, DMODEL, 0, 0, v, DMODEL, 0, 0,
            ROWS, DMODEL, DMODEL, bv + l * DMODEL, 1.f);

        // scores(b,head) = (Q_sub @ K_sub^T) / 8;  z = b*8 + head
        gemm_kernel<true,false,false><<<gemm_grid(SEQL, SEQL, BATCH*NHEAD), 256>>>(
            q, DMODEL, HB, DK, k, DMODEL, HB, DK,
            scores, SEQL, 8 * SB, SB,
            SEQL, SEQL, DK, nullptr, 0.125f);

        topk_softmax_kernel<<<BATCH*NHEAD*SEQL, 256>>>(scores);

        // attn(b,head) = P @ V_sub
        gemm_kernel<false,false,false><<<gemm_grid(SEQL, DK, BATCH*NHEAD), 256>>>(
            scores, SEQL, 8 * SB, SB, v, DMODEL, HB, DK,
            attn, DMODEL, HB, DK,
            SEQL, DK, SEQL, nullptr, 1.f);

        // proj + residual + LN1
        gemm_kernel<false,false,true><<<gemm_grid(ROWS, DMODEL, 1), 256>>>(
            attn, DMODEL, 0, 0, Wo_l, DMODEL, 0, 0, tmp2, DMODEL, 0, 0,
            ROWS, DMODEL, DMODEL, bo + l * DMODEL, 1.f);
        add_ln_kernel<<<ROWS, 256>>>(h, tmp2, h, ln1_g + l * DMODEL, ln1_b + l * DMODEL);

        // FFN
        gemm_kernel<false,true,true><<<gemm_grid(ROWS, DFF, 1), 256>>>(
            h, DMODEL, 0, 0, W1_l, DFF, 0, 0, tmp, DFF, 0, 0,
            ROWS, DFF, DMODEL, b1 + l * DFF, 1.f);
        gemm_kernel<false,false,true><<<gemm_grid(ROWS, DMODEL, 1), 256>>>(
            tmp, DFF, 0, 0, W2_l, DMODEL, 0, 0, tmp2, DMODEL, 0, 0,
            ROWS, DMODEL, DFF, b2 + l * DMODEL, 1.f);
        add_ln_kernel<<<ROWS, 256>>>(h, tmp2, h, ln2_g + l * DMODEL, ln2_b + l * DMODEL);
    }

    // decoder
    gemm_kernel<false,false,true><<<gemm_grid(ROWS, NUM_CLASSES, 1), 256>>>(
        h, DMODEL, 0, 0, W_dec, NUM_CLASSES, 0, 0, out, NUM_CLASSES, 0, 0,
        ROWS, NUM_CLASSES, DMODEL, b_dec, 1.f);
}

// round 2
// speedup vs baseline: 1.1564x; 1.1564x over previous
#include <cuda_runtime.h>
#include <mma.h>
#include <math.h>
using namespace nvcuda;

// ---------------- model dims ----------------
#define BATCH 4
#define SEQL  1024
#define DMODEL 512
#define NHEAD 8
#define DK 64
#define NLAYERS 3
#define DFF 2048
#define INPUT_DIM 128
#define NUM_CLASSES 64
#define ROWS (BATCH*SEQL)        // 4096
#define TOPU 34                  // int(5*ln(1024)) = 34

// ---------------- scratch (static device globals; no allocations) ----------------
__device__ float g_h[ROWS*DMODEL];
__device__ float g_q[ROWS*DMODEL];
__device__ float g_k[ROWS*DMODEL];
__device__ float g_v[ROWS*DMODEL];
__device__ float g_attn[ROWS*DMODEL];
__device__ float g_ff[ROWS*DFF];
__device__ float g_tmp2[ROWS*DMODEL];
__device__ float g_scores[(long long)BATCH*NHEAD*SEQL*SEQL];  // 134 MB

// ---------------- tf32(x3) tensor-core GEMM ----------------
// C = alpha * A @ B(^T). 128x128 block tile, BK=16, 256 threads (8 warps,
// 64x32 warp tiles), double-buffered smem. X3: split each operand into
// hi+lo tf32 and do 3 MMAs -> ~fp32 accuracy on the tensor pipe.
// Batched via blockIdx.z with (z/8, z%8) strides.
template<bool TRANSB, bool X3>
__global__ __launch_bounds__(256)
void mma_gemm(const float* __restrict__ A, int lda, long long sAo, long long sAi,
              const float* __restrict__ B, int ldb, long long sBo, long long sBi,
              float* __restrict__ C, int ldc, long long sCo, long long sCi,
              int M, int N, int K, float alpha)
{
    __shared__ float As[2][16][132];   // [stage][k][m]
    __shared__ float Bs[2][16][132];   // [stage][k][n]

    int z = blockIdx.z;
    A += (long long)(z >> 3) * sAo + (long long)(z & 7) * sAi;
    B += (long long)(z >> 3) * sBo + (long long)(z & 7) * sBi;
    C += (long long)(z >> 3) * sCo + (long long)(z & 7) * sCi;

    const int bm = blockIdx.y * 128, bn = blockIdx.x * 128;
    const int tid = threadIdx.x;
    const int wid = tid >> 5;
    const int wm = (wid >> 2) * 64;    // warp row offset (0 or 64)
    const int wn = (wid & 3) * 32;     // warp col offset (0..96)

    wmma::fragment<wmma::accumulator, 16, 16, 8, float> acc[4][2];
#pragma unroll
    for (int i = 0; i < 4; i++)
#pragma unroll
        for (int j = 0; j < 2; j++) wmma::fill_fragment(acc[i][j], 0.f);

    const int nk = K >> 4;

    auto load_tile = [&](int kt, int st) {
        const int k0 = kt << 4;
        // A tile: 128 x 16, float4 along k, transposed store -> As[k][m]
#pragma unroll
        for (int r = 0; r < 2; r++) {
            int idx = tid * 2 + r;           // 0..511
            int m = idx >> 2;                // 0..127
            int kq = (idx & 3) << 2;         // 0,4,8,12
            float4 v = *(const float4*)&A[(long long)(bm + m) * lda + k0 + kq];
            As[st][kq + 0][m] = v.x; As[st][kq + 1][m] = v.y;
            As[st][kq + 2][m] = v.z; As[st][kq + 3][m] = v.w;
        }
        if (!TRANSB) {
            // B tile: 16 x 128, float4 along n  (guard n for N<128 cases)
#pragma unroll
            for (int r = 0; r < 2; r++) {
                int idx = tid * 2 + r;
                int k = idx >> 5;            // 0..15
                int n4 = (idx & 31) << 2;    // 0..124
                float4 v = make_float4(0.f, 0.f, 0.f, 0.f);
                if (bn + n4 < N)
                    v = *(const float4*)&B[(long long)(k0 + k) * ldb + bn + n4];
                *(float4*)&Bs[st][k][n4] = v;
            }
        } else {
            // B is [n][k]; float4 along k, transposed store -> Bs[k][n]
#pragma unroll
            for (int r = 0; r < 2; r++) {
                int idx = tid * 2 + r;
                int n = idx >> 2;            // 0..127
                int kq = (idx & 3) << 2;
                float4 v = *(const float4*)&B[(long long)(bn + n) * ldb + k0 + kq];
                Bs[st][kq + 0][n] = v.x; Bs[st][kq + 1][n] = v.y;
                Bs[st][kq + 2][n] = v.z; Bs[st][kq + 3][n] = v.w;
            }
        }
    };

    load_tile(0, 0);
    __syncthreads();

    for (int kt = 0; kt < nk; kt++) {
        const int st = kt & 1;
        if (kt + 1 < nk) load_tile(kt + 1, st ^ 1);   // prefetch next stage

#pragma unroll
        for (int ks = 0; ks < 2; ks++) {
            wmma::fragment<wmma::matrix_b, 16, 16, 8, wmma::precision::tf32, wmma::row_major> bh[2], bl[2];
#pragma unroll
            for (int j = 0; j < 2; j++) {
                wmma::load_matrix_sync(bh[j], &Bs[st][ks * 8][wn + j * 16], 132);
                if (X3) {
#pragma unroll
                    for (int t = 0; t < bh[j].num_elements; t++) {
                        float v = bh[j].x[t];
                        float hi = wmma::__float_to_tf32(v);
                        bh[j].x[t] = hi;
                        bl[j].x[t] = wmma::__float_to_tf32(v - hi);
                    }
                } else {
#pragma unroll
                    for (int t = 0; t < bh[j].num_elements; t++)
                        bh[j].x[t] = wmma::__float_to_tf32(bh[j].x[t]);
                }
            }
#pragma unroll
            for (int i = 0; i < 4; i++) {
                wmma::fragment<wmma::matrix_a, 16, 16, 8, wmma::precision::tf32, wmma::col_major> ah, al;
                wmma::load_matrix_sync(ah, &As[st][ks * 8][wm + i * 16], 132);
                if (X3) {
#pragma unroll
                    for (int t = 0; t < ah.num_elements; t++) {
                        float v = ah.x[t];
                        float hi = wmma::__float_to_tf32(v);
                        ah.x[t] = hi;
                        al.x[t] = wmma::__float_to_tf32(v - hi);
                    }
                } else {
#pragma unroll
                    for (int t = 0; t < ah.num_elements; t++)
                        ah.x[t] = wmma::__float_to_tf32(ah.x[t]);
                }
#pragma unroll
                for (int j = 0; j < 2; j++) {
                    if (X3) {
                        wmma::mma_sync(acc[i][j], al, bh[j], acc[i][j]);
                        wmma::mma_sync(acc[i][j], ah, bl[j], acc[i][j]);
                    }
                    wmma::mma_sync(acc[i][j], ah, bh[j], acc[i][j]);
                }
            }
        }
        __syncthreads();
    }

    // epilogue: scale + store (raw; bias handled by separate fused kernels)
#pragma unroll
    for (int i = 0; i < 4; i++) {
        int gm = bm + wm + i * 16;
#pragma unroll
        for (int j = 0; j < 2; j++) {
            int gn = bn + wn + j * 16;
            if (gn < N) {
#pragma unroll
                for (int t = 0; t < acc[i][j].num_elements; t++) acc[i][j].x[t] *= alpha;
                wmma::store_matrix_sync(&C[(long long)gm * ldc + gn], acc[i][j], ldc, wmma::mem_row_major);
            }
        }
    }
}

// ---------------- X += bias (per-col) [+ relu] ----------------
template<bool RELU>
__global__ __launch_bounds__(256)
void bias_act(float* __restrict__ X, const float* __restrict__ b, int cols, int n4)
{
    int i = blockIdx.x * 256 + threadIdx.x;
    if (i >= n4) return;
    float4 v = ((float4*)X)[i];
    int c = (i * 4) % cols;
    v.x += b[c]; v.y += b[c + 1]; v.z += b[c + 2]; v.w += b[c + 3];
    if (RELU) {
        v.x = fmaxf(v.x, 0.f); v.y = fmaxf(v.y, 0.f);
        v.z = fmaxf(v.z, 0.f); v.w = fmaxf(v.w, 0.f);
    }
    ((float4*)X)[i] = v;
}

// ---------------- h = (h + b_emb)*sqrt(D) + positional encoding ----------------
__global__ __launch_bounds__(256)
void pe_kernel(float* __restrict__ h, const float* __restrict__ bemb)
{
    int row = blockIdx.x;            // 0..4095
    int pos = row & (SEQL - 1);
    const float c = 0.01798894603901634f;   // ln(10000)/512
    const float scale = 22.62741699796952f; // sqrt(512)
#pragma unroll
    for (int it = 0; it < 2; it++) {
        int col = threadIdx.x + it * 256;
        int p2 = col & ~1;
        float div = __expf(-(float)p2 * c);
        float arg = (float)pos * div;
        float pe = (col & 1) ? cosf(arg) : sinf(arg);
        long long idx = (long long)row * DMODEL + col;
        h[idx] = (h[idx] + bemb[col]) * scale + pe;
    }
}

// ---------------- out = LayerNorm(resid + delta + dbias) * g + b ----------------
__global__ __launch_bounds__(256)
void add_ln_kernel(const float* __restrict__ resid, const float* __restrict__ delta,
                   const float* __restrict__ dbias, float* __restrict__ out,
                   const float* __restrict__ g, const float* __restrict__ b)
{
    __shared__ float red[256];
    int row = blockIdx.x;
    int tid = threadIdx.x;
    long long base = (long long)row * DMODEL;
    float v0 = resid[base + tid]       + delta[base + tid]       + dbias[tid];
    float v1 = resid[base + tid + 256] + delta[base + tid + 256] + dbias[tid + 256];

    red[tid] = v0 + v1;
    __syncthreads();
    for (int s = 128; s > 0; s >>= 1) { if (tid < s) red[tid] += red[tid + s]; __syncthreads(); }
    float mean = red[0] * (1.f / DMODEL);
    __syncthreads();

    red[tid] = v0 * v0 + v1 * v1;
    __syncthreads();
    for (int s = 128; s > 0; s >>= 1) { if (tid < s) red[tid] += red[tid + s]; __syncthreads(); }
    float var = red[0] * (1.f / DMODEL) - mean * mean;
    float rstd = rsqrtf(var + 1e-5f);

    out[base + tid]       = (v0 - mean) * rstd * g[tid]       + b[tid];
    out[base + tid + 256] = (v1 - mean) * rstd * g[tid + 256] + b[tid + 256];
}

// ---------------- exact top-u threshold (radix select) + masked softmax ----------------
// One block per score row. Equivalent to where(s<kth,-1e4,s)+softmax since
// exp(-1e4 - m) == 0 in fp32. Digit selection via parallel suffix scan.
__global__ __launch_bounds__(256)
void topk_softmax_kernel(float* __restrict__ scores)
{
    __shared__ int hist[256];
    __shared__ float redf[256];
    __shared__ unsigned s_prefix;
    __shared__ int s_k;

    long long base = (long long)blockIdx.x * SEQL;
    int tid = threadIdx.x;

    float val[4];
    unsigned key[4];
#pragma unroll
    for (int i = 0; i < 4; i++) {
        val[i] = scores[base + tid + i * 256];
        unsigned bits = __float_as_uint(val[i]);
        key[i] = (bits & 0x80000000u) ? ~bits : (bits | 0x80000000u);
    }

    if (tid == 0) { s_prefix = 0u; s_k = TOPU; }
    __syncthreads();

    for (int shift = 24; shift >= 0; shift -= 8) {
        hist[tid] = 0;
        __syncthreads();
        unsigned pref = s_prefix;
        int k_cur = s_k;
#pragma unroll
        for (int i = 0; i < 4; i++) {
            bool active = (shift == 24) || ((key[i] >> (shift + 8)) == pref);
            if (active) atomicAdd(&hist[(key[i] >> shift) & 255u], 1);
        }
        __syncthreads();
        int own = hist[tid];
        // inclusive suffix scan (Hillis-Steele)
        for (int off = 1; off < 256; off <<= 1) {
            int other = (tid + off < 256) ? hist[tid + off] : 0;
            __syncthreads();
            hist[tid] += other;
            __syncthreads();
        }
        int suf = hist[tid];                 // sum of hist[tid..255]
        if (suf >= k_cur && suf - own < k_cur) {   // exactly one tid
            s_prefix = (pref << 8) | (unsigned)tid;
            s_k = k_cur - (suf - own);
        }
        __syncthreads();
    }

    unsigned tkey = s_prefix;
    unsigned tbits = (tkey & 0x80000000u) ? (tkey ^ 0x80000000u) : ~tkey;
    float thr = __uint_as_float(tbits);

    float m = -3.0e38f;
#pragma unroll
    for (int i = 0; i < 4; i++) if (val[i] >= thr) m = fmaxf(m, val[i]);
    redf[tid] = m;
    __syncthreads();
    for (int s = 128; s > 0; s >>= 1) { if (tid < s) redf[tid] = fmaxf(redf[tid], redf[tid + s]); __syncthreads(); }
    m = redf[0];
    __syncthreads();

    float e[4]; float sum = 0.f;
#pragma unroll
    for (int i = 0; i < 4; i++) {
        e[i] = (val[i] >= thr) ? __expf(val[i] - m) : 0.f;
        sum += e[i];
    }
    redf[tid] = sum;
    __syncthreads();
    for (int s = 128; s > 0; s >>= 1) { if (tid < s) redf[tid] += redf[tid + s]; __syncthreads(); }
    float inv = 1.f / redf[0];
#pragma unroll
    for (int i = 0; i < 4; i++) scores[base + tid + i * 256] = e[i] * inv;
}

// ---------------- host launch ----------------
static inline dim3 mgrid(int M, int N, int Z) {
    return dim3((N + 127) / 128, M / 128, Z);
}

extern "C" void kernel_launch(void* const* d_in, const int* in_sizes, int n_in,
                              void* d_out, int out_size)
{
    const float* x     = (const float*)d_in[0];
    const float* W_emb = (const float*)d_in[1];
    const float* b_emb = (const float*)d_in[2];
    const float* Wq    = (const float*)d_in[3];
    const float* bq    = (const float*)d_in[4];
    const float* Wk    = (const float*)d_in[5];
    const float* bk    = (const float*)d_in[6];
    const float* Wv    = (const float*)d_in[7];
    const float* bv    = (const float*)d_in[8];
    const float* Wo    = (const float*)d_in[9];
    const float* bo    = (const float*)d_in[10];
    const float* ln1_g = (const float*)d_in[11];
    const float* ln1_b = (const float*)d_in[12];
    const float* W1    = (const float*)d_in[13];
    const float* b1    = (const float*)d_in[14];
    const float* W2    = (const float*)d_in[15];
    const float* b2    = (const float*)d_in[16];
    const float* ln2_g = (const float*)d_in[17];
    const float* ln2_b = (const float*)d_in[18];
    const float* W_dec = (const float*)d_in[19];
    const float* b_dec = (const float*)d_in[20];
    float* out = (float*)d_out;

    float *h, *q, *k, *v, *attn, *ff, *tmp2, *scores;
    cudaGetSymbolAddress((void**)&h,      g_h);
    cudaGetSymbolAddress((void**)&q,      g_q);
    cudaGetSymbolAddress((void**)&k,      g_k);
    cudaGetSymbolAddress((void**)&v,      g_v);
    cudaGetSymbolAddress((void**)&attn,   g_attn);
    cudaGetSymbolAddress((void**)&ff,     g_ff);
    cudaGetSymbolAddress((void**)&tmp2,   g_tmp2);
    cudaGetSymbolAddress((void**)&scores, g_scores);

    const long long HB = (long long)SEQL * DMODEL;   // per-batch stride in Q/K/V
    const long long SB = (long long)SEQL * SEQL;     // per-(b,h) score matrix
    const int N4_D = ROWS * DMODEL / 4;              // 524288
    const int N4_F = ROWS * DFF / 4;                 // 2097152

    // embedding: h = x @ W_emb ; then (h + b_emb)*sqrt(D) + PE
    mma_gemm<false, true><<<mgrid(ROWS, DMODEL, 1), 256>>>(
        x, INPUT_DIM, 0, 0, W_emb, DMODEL, 0, 0, h, DMODEL, 0, 0,
        ROWS, DMODEL, INPUT_DIM, 1.f);
    pe_kernel<<<ROWS, 256>>>(h, b_emb);

    for (int l = 0; l < NLAYERS; l++) {
        const float* Wq_l = Wq + (long long)l * DMODEL * DMODEL;
        const float* Wk_l = Wk + (long long)l * DMODEL * DMODEL;
        const float* Wv_l = Wv + (long long)l * DMODEL * DMODEL;
        const float* Wo_l = Wo + (long long)l * DMODEL * DMODEL;
        const float* W1_l = W1 + (long long)l * DMODEL * DFF;
        const float* W2_l = W2 + (long long)l * DFF * DMODEL;

        mma_gemm<false, true><<<mgrid(ROWS, DMODEL, 1), 256>>>(
            h, DMODEL, 0, 0, Wq_l, DMODEL, 0, 0, q, DMODEL, 0, 0,
            ROWS, DMODEL, DMODEL, 1.f);
        mma_gemm<false, true><<<mgrid(ROWS, DMODEL, 1), 256>>>(
            h, DMODEL, 0, 0, Wk_l, DMODEL, 0, 0, k, DMODEL, 0, 0,
            ROWS, DMODEL, DMODEL, 1.f);
        mma_gemm<false, true><<<mgrid(ROWS, DMODEL, 1), 256>>>(
            h, DMODEL, 0, 0, Wv_l, DMODEL, 0, 0, v, DMODEL, 0, 0,
            ROWS, DMODEL, DMODEL, 1.f);
        bias_act<false><<<(N4_D + 255) / 256, 256>>>(q, bq + l * DMODEL, DMODEL, N4_D);
        bias_act<false><<<(N4_D + 255) / 256, 256>>>(k, bk + l * DMODEL, DMODEL, N4_D);
        bias_act<false><<<(N4_D + 255) / 256, 256>>>(v, bv + l * DMODEL, DMODEL, N4_D);

        // scores(b,h) = (Q_sub @ K_sub^T) / 8
        mma_gemm<true, true><<<mgrid(SEQL, SEQL, BATCH * NHEAD), 256>>>(
            q, DMODEL, HB, DK, k, DMODEL, HB, DK,
            scores, SEQL, 8 * SB, SB,
            SEQL, SEQL, DK, 0.125f);

        topk_softmax_kernel<<<BATCH * NHEAD * SEQL, 256>>>(scores);

        // attn(b,h) = P @ V_sub
        mma_gemm<false, true><<<mgrid(SEQL, DK, BATCH * NHEAD), 256>>>(
            scores, SEQL, 8 * SB, SB, v, DMODEL, HB, DK,
            attn, DMODEL, HB, DK,
            SEQL, DK, SEQL, 1.f);

        // proj; bias bo folded into add_ln
        mma_gemm<false, true><<<mgrid(ROWS, DMODEL, 1), 256>>>(
            attn, DMODEL, 0, 0, Wo_l, DMODEL, 0, 0, tmp2, DMODEL, 0, 0,
            ROWS, DMODEL, DMODEL, 1.f);
        add_ln_kernel<<<ROWS, 256>>>(h, tmp2, bo + l * DMODEL, h,
                                     ln1_g + l * DMODEL, ln1_b + l * DMODEL);

        // FFN
        mma_gemm<false, true><<<mgrid(ROWS, DFF, 1), 256>>>(
            h, DMODEL, 0, 0, W1_l, DFF, 0, 0, ff, DFF, 0, 0,
            ROWS, DFF, DMODEL, 1.f);
        bias_act<true><<<(N4_F + 255) / 256, 256>>>(ff, b1 + l * DFF, DFF, N4_F);
        mma_gemm<false, true><<<mgrid(ROWS, DMODEL, 1), 256>>>(
            ff, DFF, 0, 0, W2_l, DMODEL, 0, 0, tmp2, DMODEL, 0, 0,
            ROWS, DMODEL, DFF, 1.f);
        add_ln_kernel<<<ROWS, 256>>>(h, tmp2, b2 + l * DMODEL, h,
                                     ln2_g + l * DMODEL, ln2_b + l * DMODEL);
    }

    // decoder
    mma_gemm<false, true><<<mgrid(ROWS, NUM_CLASSES, 1), 256>>>(
        h, DMODEL, 0, 0, W_dec, NUM_CLASSES, 0, 0, out, NUM_CLASSES, 0, 0,
        ROWS, NUM_CLASSES, DMODEL, 1.f);
    bias_act<false><<<(ROWS * NUM_CLASSES / 4 + 255) / 256, 256>>>(
        out, b_dec, NUM_CLASSES, ROWS * NUM_CLASSES / 4);
}

// round 5
// speedup vs baseline: 2.6547x; 2.2956x over previous
#include <cuda_runtime.h>
#include <cuda_bf16.h>
#include <mma.h>
#include <cstdint>
#include <type_traits>
#include <math.h>
using namespace nvcuda;

#define BATCH 4
#define SEQL  1024
#define DMODEL 512
#define NHEAD 8
#define DK 64
#define NLAYERS 3
#define DFF 2048
#define INPUT_DIM 128
#define NUM_CLASSES 64
#define ROWS 4096
#define TOPU 34
#define BH 32
#define SB ((long long)SEQL*SEQL)
#define BK 32
typedef __nv_bfloat16 bf16;

// ---------------- scratch (static device globals) ----------------
__device__ __align__(16) float g_h [DMODEL*ROWS];     // h_t  [feature][token] fp32
__device__ __align__(16) float g_t2[DMODEL*ROWS];     // tmp2_t fp32
__device__ __align__(16) float g_sc[(long long)BH*SB];
__device__ __align__(16) float g_bcat[2*DMODEL];
__device__ __align__(16) bf16 g_x0[INPUT_DIM*ROWS], g_x1[INPUT_DIM*ROWS];     // x_t planes
__device__ __align__(16) bf16 g_h0[DMODEL*ROWS],  g_h1[DMODEL*ROWS];          // h_t planes
__device__ __align__(16) bf16 g_qk0[2*DMODEL*ROWS], g_qk1[2*DMODEL*ROWS];     // Q_t then K_t
__device__ __align__(16) bf16 g_v0[ROWS*DMODEL],  g_v1[ROWS*DMODEL];          // V token-major
__device__ __align__(16) bf16 g_a0[DMODEL*ROWS],  g_a1[DMODEL*ROWS];          // attn_t planes
__device__ __align__(16) bf16 g_f0[DFF*ROWS],     g_f1[DFF*ROWS];             // ff_t planes
__device__ __align__(16) bf16 g_P0[(long long)BH*SB], g_P1[(long long)BH*SB]; // P row-major
#define W_EMB 0
#define W_LAYER(l) (65536 + (long long)(l)*3145728)
#define W_Q 0
#define W_K 262144
#define W_V 524288
#define W_O 786432
#define W_1 1048576
#define W_2 2097152
#define W_DEC (65536 + 3LL*3145728)
#define WT_TOTAL (65536 + 3*3145728 + 32768)
__device__ __align__(16) bf16 g_w0[WT_TOTAL], g_w1[WT_TOTAL];

// ---------------- helpers ----------------
__device__ __forceinline__ uint32_t smem_to_u32(const void* p) {
    uint32_t a;
    asm("{ .reg .u64 t; cvta.to.shared.u64 t, %1; cvt.u32.u64 %0, t; }" : "=r"(a) : "l"(p));
    return a;
}
__device__ __forceinline__ void cp16(uint32_t s, const bf16* g) {
    asm volatile("{ .reg .u64 p; cvta.to.global.u64 p, %1; cp.async.cg.shared.global [%0], [p], 16; }"
                 :: "r"(s), "l"(g) : "memory");
}
__device__ __forceinline__ void cp_commit() { asm volatile("cp.async.commit_group;" ::: "memory"); }
__device__ __forceinline__ void cp_wait1()  { asm volatile("cp.async.wait_group 1;" ::: "memory"); }
__device__ __forceinline__ void cp_wait0()  { asm volatile("cp.async.wait_group 0;" ::: "memory"); }

__device__ __forceinline__ void split2(float v, bf16& s0, bf16& s1) {
    s0 = __float2bfloat16_rn(v);
    s1 = __float2bfloat16_rn(v - __bfloat162float(s0));
}

// ---------------- bf16x2 tensor GEMM ----------------
// C[M][N] = alpha * sum_k (A0+A1)[k][m] * (B0+B1)[k][n]   (3 products)
// A global: [K][Mglob]. B: [K][Nglob] (BCOL=0) or [Nglob][K] (BCOL=1).
// BIAS: 0 none, 1 per-M-row, 2 per-N-col. EPI: 0 fp32 out, 1 split2 bf16 out.
template<int MT, int NT, int BIAS, int EPI, bool BCOL, bool RELU>
__global__ __launch_bounds__(256, 2)
void gk(const bf16* __restrict__ A0, const bf16* __restrict__ A1,
        int lda, long long sAo, long long sAi,
        const bf16* __restrict__ B0, const bf16* __restrict__ B1,
        int ldb, long long sBo, long long sBi,
        float* __restrict__ C, bf16* __restrict__ C0, bf16* __restrict__ C1,
        int ldc, long long sCo, long long sCi,
        int K, const float* __restrict__ bias, long long sBias, float alpha)
{
    extern __shared__ char smc[];
    constexpr int LA = MT + 8;
    constexpr int SZA = BK * LA;                         // elems, per plane-stage
    constexpr int LB = BCOL ? (BK + 8) : (NT + 8);
    constexpr int SZB = BCOL ? (NT * LB) : (BK * LB);
    constexpr int A_ELEMS = 4 * SZA;                     // 2 stages x 2 planes
    constexpr int LS = NT + 4;                           // staging ld (fp32)
    bf16* As = (bf16*)smc;
    bf16* Bs = As + A_ELEMS;
    float* stg = (float*)smc;

    const uint32_t smb = smem_to_u32(smc);
    const uint32_t smB = smb + A_ELEMS * 2;
    const int tid = threadIdx.x, wid = tid >> 5;
    const int z = blockIdx.z;
    const int bm = blockIdx.y * MT, bn = blockIdx.x * NT;
    const long long zA = (long long)(z >> 3) * sAo + (long long)(z & 7) * sAi;
    const long long zB = (long long)(z >> 3) * sBo + (long long)(z & 7) * sBi;
    const long long zC = (long long)(z >> 3) * sCo + (long long)(z & 7) * sCi;
    const bf16* Ap[2] = { A0 + zA, A1 + zA };
    const bf16* Bp[2] = { B0 + zB, B1 + zB };

    // warp tiling: WN_CNT warps across N (32 cols each), 8/WN_CNT groups across M
    constexpr int WN_CNT = NT / 32;
    constexpr int WM = MT * WN_CNT / 8;
    constexpr int FM = WM / 16;
    const int wm = (wid / WN_CNT) * WM;
    const int wn = (wid % WN_CNT) * 32;

    using FragA = wmma::fragment<wmma::matrix_a, 16, 16, 16, bf16, wmma::col_major>;
    using BLay  = typename std::conditional<BCOL, wmma::col_major, wmma::row_major>::type;
    using FragB = wmma::fragment<wmma::matrix_b, 16, 16, 16, bf16, BLay>;
    wmma::fragment<wmma::accumulator, 16, 16, 16, float> acc[FM][2];
#pragma unroll
    for (int i = 0; i < FM; i++)
#pragma unroll
        for (int j = 0; j < 2; j++) wmma::fill_fragment(acc[i][j], 0.f);

    auto load_stage = [&](int c, int st) {
        const int k0 = c * BK;
#pragma unroll
        for (int p = 0; p < 2; p++) {
            const bf16* ap = Ap[p];
            for (int t = tid; t < 4 * MT; t += 256) {
                int k = t / (MT / 8), ch = t % (MT / 8);
                uint32_t d = smb + (uint32_t)(((st * 2 + p) * SZA + k * LA + ch * 8) * 2);
                cp16(d, ap + (long long)(k0 + k) * lda + bm + ch * 8);
            }
            const bf16* bp = Bp[p];
            if (!BCOL) {
                for (int t = tid; t < 4 * NT; t += 256) {
                    int k = t / (NT / 8), ch = t % (NT / 8);
                    uint32_t d = smB + (uint32_t)(((st * 2 + p) * SZB + k * LB + ch * 8) * 2);
                    cp16(d, bp + (long long)(k0 + k) * ldb + bn + ch * 8);
                }
            } else {
                for (int t = tid; t < 4 * NT; t += 256) {
                    int n = t >> 2, ch = t & 3;
                    uint32_t d = smB + (uint32_t)(((st * 2 + p) * SZB + n * LB + ch * 8) * 2);
                    cp16(d, bp + (long long)(bn + n) * ldb + k0 + ch * 8);
                }
            }
        }
        cp_commit();
    };

    const int nch = K / BK;
    load_stage(0, 0);

    for (int c = 0; c < nch; c++) {
        const int st = c & 1;
        if (c + 1 < nch) { load_stage(c + 1, st ^ 1); cp_wait1(); }
        else cp_wait0();
        __syncthreads();
#pragma unroll
        for (int ks = 0; ks < 2; ks++) {
            FragB bfr[2][2];
#pragma unroll
            for (int p = 0; p < 2; p++)
#pragma unroll
                for (int j = 0; j < 2; j++) {
                    const bf16* ptr = Bs + (st * 2 + p) * SZB +
                        (BCOL ? ((wn + j * 16) * LB + ks * 16) : (ks * 16 * LB + wn + j * 16));
                    wmma::load_matrix_sync(bfr[p][j], ptr, LB);
                }
#pragma unroll
            for (int i = 0; i < FM; i++) {
                FragA a0, a1;
                wmma::load_matrix_sync(a0, As + (st * 2 + 0) * SZA + ks * 16 * LA + wm + i * 16, LA);
                wmma::load_matrix_sync(a1, As + (st * 2 + 1) * SZA + ks * 16 * LA + wm + i * 16, LA);
#pragma unroll
                for (int j = 0; j < 2; j++) {
                    wmma::mma_sync(acc[i][j], a0, bfr[0][j], acc[i][j]);
                    wmma::mma_sync(acc[i][j], a0, bfr[1][j], acc[i][j]);
                    wmma::mma_sync(acc[i][j], a1, bfr[0][j], acc[i][j]);
                }
            }
        }
        __syncthreads();
    }

    // ---- staged epilogue (overlay pipeline smem) ----
#pragma unroll
    for (int i = 0; i < FM; i++)
#pragma unroll
        for (int j = 0; j < 2; j++)
            wmma::store_matrix_sync(&stg[(wm + i * 16) * LS + wn + j * 16], acc[i][j], LS, wmma::mem_row_major);
    __syncthreads();

    for (int t = tid; t < MT * NT / 4; t += 256) {
        int row = t / (NT / 4), c4 = (t % (NT / 4)) * 4;
        float4 v = *(float4*)&stg[row * LS + c4];
        v.x *= alpha; v.y *= alpha; v.z *= alpha; v.w *= alpha;
        if (BIAS == 1) {
            float bb = bias[(z & 7) * sBias + bm + row];
            v.x += bb; v.y += bb; v.z += bb; v.w += bb;
        } else if (BIAS == 2) {
            const float* bp = bias + (z & 7) * sBias + bn + c4;
            v.x += bp[0]; v.y += bp[1]; v.z += bp[2]; v.w += bp[3];
        }
        if (RELU) {
            v.x = fmaxf(v.x, 0.f); v.y = fmaxf(v.y, 0.f);
            v.z = fmaxf(v.z, 0.f); v.w = fmaxf(v.w, 0.f);
        }
        long long idx = zC + (long long)(bm + row) * ldc + bn + c4;
        if (EPI == 0) {
            *(float4*)&C[idx] = v;
        } else {
            union { uint2 u; bf16 h[4]; } p0, p1;
            split2(v.x, p0.h[0], p1.h[0]);
            split2(v.y, p0.h[1], p1.h[1]);
            split2(v.z, p0.h[2], p1.h[2]);
            split2(v.w, p0.h[3], p1.h[3]);
            *(uint2*)&C0[idx] = p0.u;
            *(uint2*)&C1[idx] = p1.u;
        }
    }
}

// ---------------- elementwise / reduction kernels ----------------
__global__ __launch_bounds__(256)
void wsplit(const float* __restrict__ W, bf16* __restrict__ o0, bf16* __restrict__ o1, int n)
{
    int i = blockIdx.x * 256 + threadIdx.x;
    if (i >= n) return;
    bf16 s0, s1; split2(W[i], s0, s1);
    o0[i] = s0; o1[i] = s1;
}

__global__ __launch_bounds__(256)
void xsplit_t(const float* __restrict__ x, bf16* __restrict__ o0, bf16* __restrict__ o1)
{
    __shared__ float t[32][33];
    int m0 = blockIdx.x * 32, f0 = blockIdx.y * 32;
    int tx = threadIdx.x & 31, ty = threadIdx.x >> 5;
#pragma unroll
    for (int i = 0; i < 4; i++)
        t[ty + 8 * i][tx] = x[(long long)(m0 + ty + 8 * i) * INPUT_DIM + f0 + tx];
    __syncthreads();
#pragma unroll
    for (int i = 0; i < 4; i++) {
        float v = t[tx][ty + 8 * i];
        long long idx = (long long)(f0 + ty + 8 * i) * ROWS + m0 + tx;
        bf16 s0, s1; split2(v, s0, s1);
        o0[idx] = s0; o1[idx] = s1;
    }
}

__global__ __launch_bounds__(256)
void pe_t(float* __restrict__ h, const float* __restrict__ bemb,
          bf16* __restrict__ o0, bf16* __restrict__ o1)
{
    int f = blockIdx.x;
    const float cc = 0.01798894603901634f;     // ln(10000)/512
    const float scale = 22.62741699796952f;    // sqrt(512)
    float div = __expf(-(float)(f & ~1) * cc);
    bool odd = f & 1;
    float bb = bemb[f];
    for (int m = threadIdx.x; m < ROWS; m += 256) {
        int pos = m & (SEQL - 1);
        float arg = (float)pos * div;
        float pe = odd ? cosf(arg) : sinf(arg);
        long long idx = (long long)f * ROWS + m;
        float v = (h[idx] + bb) * scale + pe;
        h[idx] = v;
        bf16 s0, s1; split2(v, s0, s1);
        o0[idx] = s0; o1[idx] = s1;
    }
}

// feature-major LN over features: block = 32 tokens
__global__ __launch_bounds__(256)
void add_ln_t(const float* __restrict__ resid, const float* __restrict__ delta,
              const float* __restrict__ dbias, float* __restrict__ out,
              bf16* __restrict__ o0, bf16* __restrict__ o1,
              const float* __restrict__ g, const float* __restrict__ b)
{
    __shared__ float S[8][32], S2[8][32], Sm[32], Sr[32];
    int m = blockIdx.x * 32 + (threadIdx.x & 31);
    int w = threadIdx.x >> 5;
    float s = 0.f, s2 = 0.f;
    for (int jj = 0; jj < 64; jj++) {
        int f = w * 64 + jj;
        float v = resid[(long long)f * ROWS + m] + delta[(long long)f * ROWS + m] + dbias[f];
        s += v; s2 += v * v;
    }
    S[w][threadIdx.x & 31] = s; S2[w][threadIdx.x & 31] = s2;
    __syncthreads();
    if (threadIdx.x < 32) {
        float a = 0.f, c = 0.f;
#pragma unroll
        for (int ww = 0; ww < 8; ww++) { a += S[ww][threadIdx.x]; c += S2[ww][threadIdx.x]; }
        float mean = a * (1.f / DMODEL);
        float var = c * (1.f / DMODEL) - mean * mean;
        Sm[threadIdx.x] = mean; Sr[threadIdx.x] = rsqrtf(var + 1e-5f);
    }
    __syncthreads();
    float mean = Sm[threadIdx.x & 31], rstd = Sr[threadIdx.x & 31];
    for (int jj = 0; jj < 64; jj++) {
        int f = w * 64 + jj;
        long long idx = (long long)f * ROWS + m;
        float v = resid[idx] + delta[idx] + dbias[f];
        float o = (v - mean) * rstd * g[f] + b[f];
        out[idx] = o;
        bf16 s0, s1; split2(o, s0, s1);
        o0[idx] = s0; o1[idx] = s1;
    }
}

__global__ void cat2(const float* __restrict__ a, const float* __restrict__ b, float* __restrict__ o)
{
    int i = blockIdx.x * 256 + threadIdx.x;
    if (i < DMODEL) o[i] = a[i];
    else if (i < 2 * DMODEL) o[i] = b[i - DMODEL];
}

// ---------------- exact top-u radix select + masked softmax -> P split2 ----------------
__global__ __launch_bounds__(256)
void topk_softmax_kernel(const float* __restrict__ scores,
                         bf16* __restrict__ P0, bf16* __restrict__ P1)
{
    __shared__ int hist[256];
    __shared__ float redf[256];
    __shared__ unsigned s_prefix;
    __shared__ int s_k;

    long long base = (long long)blockIdx.x * SEQL;
    int tid = threadIdx.x;
    float val[4];
    unsigned key[4];
#pragma unroll
    for (int i = 0; i < 4; i++) {
        val[i] = scores[base + tid + i * 256];
        unsigned bits = __float_as_uint(val[i]);
        key[i] = (bits & 0x80000000u) ? ~bits : (bits | 0x80000000u);
    }
    if (tid == 0) { s_prefix = 0u; s_k = TOPU; }
    __syncthreads();
    for (int shift = 24; shift >= 0; shift -= 8) {
        hist[tid] = 0;
        __syncthreads();
        unsigned pref = s_prefix;
        int k_cur = s_k;
#pragma unroll
        for (int i = 0; i < 4; i++) {
            bool active = (shift == 24) || ((key[i] >> (shift + 8)) == pref);
            if (active) atomicAdd(&hist[(key[i] >> shift) & 255u], 1);
        }
        __syncthreads();
        int own = hist[tid];
        for (int off = 1; off < 256; off <<= 1) {
            int other = (tid + off < 256) ? hist[tid + off] : 0;
            __syncthreads();
            hist[tid] += other;
            __syncthreads();
        }
        int suf = hist[tid];
        if (suf >= k_cur && suf - own < k_cur) {
            s_prefix = (pref << 8) | (unsigned)tid;
            s_k = k_cur - (suf - own);
        }
        __syncthreads();
    }
    unsigned tkey = s_prefix;
    unsigned tbits = (tkey & 0x80000000u) ? (tkey ^ 0x80000000u) : ~tkey;
    float thr = __uint_as_float(tbits);

    float m = -3.0e38f;
#pragma unroll
    for (int i = 0; i < 4; i++) if (val[i] >= thr) m = fmaxf(m, val[i]);
    redf[tid] = m;
    __syncthreads();
    for (int s = 128; s > 0; s >>= 1) { if (tid < s) redf[tid] = fmaxf(redf[tid], redf[tid + s]); __syncthreads(); }
    m = redf[0];
    __syncthreads();
    float e[4]; float sum = 0.f;
#pragma unroll
    for (int i = 0; i < 4; i++) {
        e[i] = (val[i] >= thr) ? __expf(val[i] - m) : 0.f;
        sum += e[i];
    }
    redf[tid] = sum;
    __syncthreads();
    for (int s = 128; s > 0; s >>= 1) { if (tid < s) redf[tid] += redf[tid + s]; __syncthreads(); }
    float inv = 1.f / redf[0];
#pragma unroll
    for (int i = 0; i < 4; i++) {
        float p = e[i] * inv;
        bf16 s0, s1; split2(p, s0, s1);
        P0[base + tid + i * 256] = s0;
        P1[base + tid + i * 256] = s1;
    }
}

// ---------------- host launch ----------------
extern "C" void kernel_launch(void* const* d_in, const int* in_sizes, int n_in,
                              void* d_out, int out_size)
{
    const float* x     = (const float*)d_in[0];
    const float* W_emb = (const float*)d_in[1];
    const float* b_emb = (const float*)d_in[2];
    const float* Wq    = (const float*)d_in[3];
    const float* bq    = (const float*)d_in[4];
    const float* Wk    = (const float*)d_in[5];
    const float* bk    = (const float*)d_in[6];
    const float* Wv    = (const float*)d_in[7];
    const float* bv    = (const float*)d_in[8];
    const float* Wo    = (const float*)d_in[9];
    const float* bo    = (const float*)d_in[10];
    const float* ln1_g = (const float*)d_in[11];
    const float* ln1_b = (const float*)d_in[12];
    const float* W1    = (const float*)d_in[13];
    const float* b1    = (const float*)d_in[14];
    const float* W2    = (const float*)d_in[15];
    const float* b2    = (const float*)d_in[16];
    const float* ln2_g = (const float*)d_in[17];
    const float* ln2_b = (const float*)d_in[18];
    const float* W_dec = (const float*)d_in[19];
    const float* b_dec = (const float*)d_in[20];
    float* out = (float*)d_out;

    float *h, *t2, *sc, *bcat;
    bf16 *x0, *x1, *h0, *h1, *qk0, *qk1, *v0, *v1, *a0, *a1, *f0, *f1, *P0, *P1, *w0, *w1;
    cudaGetSymbolAddress((void**)&h, g_h);
    cudaGetSymbolAddress((void**)&t2, g_t2);
    cudaGetSymbolAddress((void**)&sc, g_sc);
    cudaGetSymbolAddress((void**)&bcat, g_bcat);
    cudaGetSymbolAddress((void**)&x0, g_x0);  cudaGetSymbolAddress((void**)&x1, g_x1);
    cudaGetSymbolAddress((void**)&h0, g_h0);  cudaGetSymbolAddress((void**)&h1, g_h1);
    cudaGetSymbolAddress((void**)&qk0, g_qk0); cudaGetSymbolAddress((void**)&qk1, g_qk1);
    cudaGetSymbolAddress((void**)&v0, g_v0);  cudaGetSymbolAddress((void**)&v1, g_v1);
    cudaGetSymbolAddress((void**)&a0, g_a0);  cudaGetSymbolAddress((void**)&a1, g_a1);
    cudaGetSymbolAddress((void**)&f0, g_f0);  cudaGetSymbolAddress((void**)&f1, g_f1);
    cudaGetSymbolAddress((void**)&P0, g_P0);  cudaGetSymbolAddress((void**)&P1, g_P1);
    cudaGetSymbolAddress((void**)&w0, g_w0);  cudaGetSymbolAddress((void**)&w1, g_w1);

    // instantiations + smem
    auto k64f  = gk<64, 128, 0, 0, false, false>;   // emb / proj / FF2
    auto kQK   = gk<64, 128, 1, 1, false, false>;
    auto kV    = gk<64, 128, 2, 1, false, false>;
    auto kSc   = gk<128, 128, 0, 0, false, false>;
    auto kPV   = gk<64, 128, 0, 1, true,  false>;
    auto kFF1  = gk<128, 128, 1, 1, false, true>;
    auto kDec  = gk<128, 64, 2, 0, false, false>;
    const int SM64  = 53248;
    const int SM128 = 69632;
    const int SMPV  = 59392;
    cudaFuncSetAttribute(k64f, cudaFuncAttributeMaxDynamicSharedMemorySize, SM64);
    cudaFuncSetAttribute(kQK,  cudaFuncAttributeMaxDynamicSharedMemorySize, SM64);
    cudaFuncSetAttribute(kV,   cudaFuncAttributeMaxDynamicSharedMemorySize, SM64);
    cudaFuncSetAttribute(kSc,  cudaFuncAttributeMaxDynamicSharedMemorySize, SM128);
    cudaFuncSetAttribute(kPV,  cudaFuncAttributeMaxDynamicSharedMemorySize, SMPV);
    cudaFuncSetAttribute(kFF1, cudaFuncAttributeMaxDynamicSharedMemorySize, SM128);
    cudaFuncSetAttribute(kDec, cudaFuncAttributeMaxDynamicSharedMemorySize, SM64);

    // ---- weight splits (native layout, elementwise) ----
    wsplit<<<(65536 + 255) / 256, 256>>>(W_emb, w0 + W_EMB, w1 + W_EMB, 65536);
    for (int l = 0; l < NLAYERS; l++) {
        long long wb = W_LAYER(l);
        wsplit<<<1024, 256>>>(Wq + (long long)l * 262144, w0 + wb + W_Q, w1 + wb + W_Q, 262144);
        wsplit<<<1024, 256>>>(Wk + (long long)l * 262144, w0 + wb + W_K, w1 + wb + W_K, 262144);
        wsplit<<<1024, 256>>>(Wv + (long long)l * 262144, w0 + wb + W_V, w1 + wb + W_V, 262144);
        wsplit<<<1024, 256>>>(Wo + (long long)l * 262144, w0 + wb + W_O, w1 + wb + W_O, 262144);
        wsplit<<<4096, 256>>>(W1 + (long long)l * 1048576, w0 + wb + W_1, w1 + wb + W_1, 1048576);
        wsplit<<<4096, 256>>>(W2 + (long long)l * 1048576, w0 + wb + W_2, w1 + wb + W_2, 1048576);
    }
    wsplit<<<128, 256>>>(W_dec, w0 + W_DEC, w1 + W_DEC, 32768);

    // ---- x transpose+split, embedding ----
    xsplit_t<<<dim3(ROWS / 32, INPUT_DIM / 32), 256>>>(x, x0, x1);
    k64f<<<dim3(32, 8, 1), 256, SM64>>>(
        w0 + W_EMB, w1 + W_EMB, DMODEL, 0, 0,
        x0, x1, ROWS, 0, 0,
        h, nullptr, nullptr, ROWS, 0, 0,
        INPUT_DIM, nullptr, 0, 1.f);
    pe_t<<<DMODEL, 256>>>(h, b_emb, h0, h1);

    const long long QKOFF = (long long)DMODEL * ROWS;   // K plane offset in qk arena

    for (int l = 0; l < NLAYERS; l++) {
        long long wb = W_LAYER(l);
        cat2<<<4, 256>>>(bq + l * DMODEL, bk + l * DMODEL, bcat);
        // Q_t, K_t (fused, z selects weight/output/bias)
        kQK<<<dim3(32, 8, 2), 256, SM64>>>(
            w0 + wb + W_Q, w1 + wb + W_Q, DMODEL, 0, 262144,
            h0, h1, ROWS, 0, 0,
            nullptr, qk0, qk1, ROWS, 0, QKOFF,
            DMODEL, bcat, DMODEL, 1.f);
        // V (token-major out)
        kV<<<dim3(4, 64, 1), 256, SM64>>>(
            h0, h1, ROWS, 0, 0,
            w0 + wb + W_V, w1 + wb + W_V, DMODEL, 0, 0,
            nullptr, v0, v1, DMODEL, 0, 0,
            DMODEL, bv + l * DMODEL, 0, 1.f);
        // scores = (Q^T K) / 8 per (b,h)
        kSc<<<dim3(8, 8, BH), 256, SM128>>>(
            qk0, qk1, ROWS, SEQL, (long long)DK * ROWS,
            qk0 + QKOFF, qk1 + QKOFF, ROWS, SEQL, (long long)DK * ROWS,
            sc, nullptr, nullptr, SEQL, 8 * SB, SB,
            DK, nullptr, 0, 0.125f);
        topk_softmax_kernel<<<BH * SEQL, 256>>>(sc, P0, P1);
        // attn_t = V^T @ P^T  (B = P via col-major fragments)
        kPV<<<dim3(8, 1, BH), 256, SMPV>>>(
            v0, v1, DMODEL, (long long)SEQL * DMODEL, DK,
            P0, P1, SEQL, 8 * SB, SB,
            nullptr, a0, a1, ROWS, SEQL, (long long)DK * ROWS,
            SEQL, nullptr, 0, 1.f);
        // proj
        k64f<<<dim3(32, 8, 1), 256, SM64>>>(
            w0 + wb + W_O, w1 + wb + W_O, DMODEL, 0, 0,
            a0, a1, ROWS, 0, 0,
            t2, nullptr, nullptr, ROWS, 0, 0,
            DMODEL, nullptr, 0, 1.f);
        add_ln_t<<<ROWS / 32, 256>>>(h, t2, bo + l * DMODEL, h, h0, h1,
                                     ln1_g + l * DMODEL, ln1_b + l * DMODEL);
        // FF1 (bias row + relu + split)
        kFF1<<<dim3(32, 16, 1), 256, SM128>>>(
            w0 + wb + W_1, w1 + wb + W_1, DFF, 0, 0,
            h0, h1, ROWS, 0, 0,
            nullptr, f0, f1, ROWS, 0, 0,
            DMODEL, b1 + l * DFF, 0, 1.f);
        // FF2
        k64f<<<dim3(32, 8, 1), 256, SM64>>>(
            w0 + wb + W_2, w1 + wb + W_2, DMODEL, 0, 0,
            f0, f1, ROWS, 0, 0,
            t2, nullptr, nullptr, ROWS, 0, 0,
            DFF, nullptr, 0, 1.f);
        add_ln_t<<<ROWS / 32, 256>>>(h, t2, b2 + l * DMODEL, h, h0, h1,
                                     ln2_g + l * DMODEL, ln2_b + l * DMODEL);
    }

    // decoder: out[token][class]
    kDec<<<dim3(1, 32, 1), 256, SM64>>>(
        h0, h1, ROWS, 0, 0,
        w0 + W_DEC, w1 + W_DEC, NUM_CLASSES, 0, 0,
        out, nullptr, nullptr, NUM_CLASSES, 0, 0,
        DMODEL, b_dec, 0, 1.f);
}

// round 6
// speedup vs baseline: 2.7115x; 1.0214x over previous
#include <cuda_runtime.h>
#include <cuda_bf16.h>
#include <mma.h>
#include <cstdint>
#include <type_traits>
#include <math.h>
using namespace nvcuda;

#define BATCH 4
#define SEQL  1024
#define DMODEL 512
#define NHEAD 8
#define DK 64
#define NLAYERS 3
#define DFF 2048
#define INPUT_DIM 128
#define NUM_CLASSES 64
#define ROWS 4096
#define TOPU 34
#define BH 32
#define SB ((long long)SEQL*SEQL)
#define BK 32
#define NSTG 3
typedef __nv_bfloat16 bf16;

// ---------------- scratch (static device globals) ----------------
__device__ __align__(16) float g_h [DMODEL*ROWS];     // h_t  [feature][token] fp32
__device__ __align__(16) float g_t2[DMODEL*ROWS];     // tmp2_t fp32
__device__ __align__(16) float g_sc[(long long)BH*SB];
__device__ __align__(16) float g_bcat[NLAYERS*2*DMODEL];
__device__ __align__(16) bf16 g_x0[INPUT_DIM*ROWS], g_x1[INPUT_DIM*ROWS];     // x_t planes
__device__ __align__(16) bf16 g_h0[DMODEL*ROWS],  g_h1[DMODEL*ROWS];          // h_t planes
__device__ __align__(16) bf16 g_qk0[2*DMODEL*ROWS], g_qk1[2*DMODEL*ROWS];     // Q_t then K_t
__device__ __align__(16) bf16 g_v0[ROWS*DMODEL],  g_v1[ROWS*DMODEL];          // V token-major
__device__ __align__(16) bf16 g_a0[DMODEL*ROWS],  g_a1[DMODEL*ROWS];          // attn_t planes
__device__ __align__(16) bf16 g_f0[DFF*ROWS],     g_f1[DFF*ROWS];             // ff_t planes
__device__ __align__(16) bf16 g_P0[(long long)BH*SB], g_P1[(long long)BH*SB]; // P row-major

// weight arena: [emb][Q x3][K x3][V x3][O x3][W1 x3][W2 x3][dec]
#define W_EMB 0
#define W_Qo(l) (65536LL   + (long long)(l)*262144)
#define W_Ko(l) (851968LL  + (long long)(l)*262144)
#define W_Vo(l) (1638400LL + (long long)(l)*262144)
#define W_Oo(l) (2424832LL + (long long)(l)*262144)
#define W_1o(l) (3211264LL + (long long)(l)*1048576)
#define W_2o(l) (6356992LL + (long long)(l)*1048576)
#define W_DEC 9502720LL
#define WT_TOTAL 9535488LL
__device__ __align__(16) bf16 g_w0[WT_TOTAL], g_w1[WT_TOTAL];

// ---------------- helpers ----------------
__device__ __forceinline__ uint32_t smem_to_u32(const void* p) {
    uint32_t a;
    asm("{ .reg .u64 t; cvta.to.shared.u64 t, %1; cvt.u32.u64 %0, t; }" : "=r"(a) : "l"(p));
    return a;
}
__device__ __forceinline__ void cp16(uint32_t s, const bf16* g) {
    asm volatile("{ .reg .u64 p; cvta.to.global.u64 p, %1; cp.async.cg.shared.global [%0], [p], 16; }"
                 :: "r"(s), "l"(g) : "memory");
}
__device__ __forceinline__ void cp_commit() { asm volatile("cp.async.commit_group;" ::: "memory"); }
__device__ __forceinline__ void cp_wait2()  { asm volatile("cp.async.wait_group 2;" ::: "memory"); }
__device__ __forceinline__ void cp_wait1()  { asm volatile("cp.async.wait_group 1;" ::: "memory"); }
__device__ __forceinline__ void cp_wait0()  { asm volatile("cp.async.wait_group 0;" ::: "memory"); }

__device__ __forceinline__ void split2(float v, bf16& s0, bf16& s1) {
    s0 = __float2bfloat16_rn(v);
    s1 = __float2bfloat16_rn(v - __bfloat162float(s0));
}

// ---------------- bf16x2 tensor GEMM (3-stage cp.async pipeline) ----------------
// C[M][N] = alpha * sum_k (A0+A1)[k][m] * (B0+B1)[k][n]   (3 products)
// A global: [K][Mglob]. B: [K][Nglob] (BCOL=0) or [Nglob][K] (BCOL=1).
// BIAS: 0 none, 1 per-M-row, 2 per-N-col. EPI: 0 fp32 out, 1 split2 bf16 out.
template<int MT, int NT, int BIAS, int EPI, bool BCOL, bool RELU>
__global__ __launch_bounds__(256, 2)
void gk(const bf16* __restrict__ A0, const bf16* __restrict__ A1,
        int lda, long long sAo, long long sAi,
        const bf16* __restrict__ B0, const bf16* __restrict__ B1,
        int ldb, long long sBo, long long sBi,
        float* __restrict__ C, bf16* __restrict__ C0, bf16* __restrict__ C1,
        int ldc, long long sCo, long long sCi,
        int K, const float* __restrict__ bias, long long sBias, float alpha)
{
    extern __shared__ char smc[];
    constexpr int LA = MT + 8;
    constexpr int SZA = BK * LA;                         // elems, per plane-stage
    constexpr int LB = BCOL ? (BK + 8) : (NT + 8);
    constexpr int SZB = BCOL ? (NT * LB) : (BK * LB);
    constexpr int A_ELEMS = NSTG * 2 * SZA;              // stages x planes
    constexpr int LS = NT + 4;                           // staging ld (fp32)
    bf16* As = (bf16*)smc;
    bf16* Bs = As + A_ELEMS;
    float* stg = (float*)smc;

    const uint32_t smb = smem_to_u32(smc);
    const uint32_t smB = smb + A_ELEMS * 2;
    const int tid = threadIdx.x, wid = tid >> 5;
    const int z = blockIdx.z;
    const int bm = blockIdx.y * MT, bn = blockIdx.x * NT;
    const long long zA = (long long)(z >> 3) * sAo + (long long)(z & 7) * sAi;
    const long long zB = (long long)(z >> 3) * sBo + (long long)(z & 7) * sBi;
    const long long zC = (long long)(z >> 3) * sCo + (long long)(z & 7) * sCi;
    const bf16* Ap[2] = { A0 + zA, A1 + zA };
    const bf16* Bp[2] = { B0 + zB, B1 + zB };

    // warp tiling: WN_CNT warps across N (32 cols each), 8/WN_CNT groups across M
    constexpr int WN_CNT = NT / 32;
    constexpr int WM = MT * WN_CNT / 8;
    constexpr int FM = WM / 16;
    const int wm = (wid / WN_CNT) * WM;
    const int wn = (wid % WN_CNT) * 32;

    using FragA = wmma::fragment<wmma::matrix_a, 16, 16, 16, bf16, wmma::col_major>;
    using BLay  = typename std::conditional<BCOL, wmma::col_major, wmma::row_major>::type;
    using FragB = wmma::fragment<wmma::matrix_b, 16, 16, 16, bf16, BLay>;
    wmma::fragment<wmma::accumulator, 16, 16, 16, float> acc[FM][2];
#pragma unroll
    for (int i = 0; i < FM; i++)
#pragma unroll
        for (int j = 0; j < 2; j++) wmma::fill_fragment(acc[i][j], 0.f);

    auto load_stage = [&](int c, int st) {
        const int k0 = c * BK;
#pragma unroll
        for (int p = 0; p < 2; p++) {
            const bf16* ap = Ap[p];
            for (int t = tid; t < 4 * MT; t += 256) {
                int k = t / (MT / 8), ch = t % (MT / 8);
                uint32_t d = smb + (uint32_t)(((st * 2 + p) * SZA + k * LA + ch * 8) * 2);
                cp16(d, ap + (long long)(k0 + k) * lda + bm + ch * 8);
            }
            const bf16* bp = Bp[p];
            if (!BCOL) {
                for (int t = tid; t < 4 * NT; t += 256) {
                    int k = t / (NT / 8), ch = t % (NT / 8);
                    uint32_t d = smB + (uint32_t)(((st * 2 + p) * SZB + k * LB + ch * 8) * 2);
                    cp16(d, bp + (long long)(k0 + k) * ldb + bn + ch * 8);
                }
            } else {
                for (int t = tid; t < 4 * NT; t += 256) {
                    int n = t >> 2, ch = t & 3;
                    uint32_t d = smB + (uint32_t)(((st * 2 + p) * SZB + n * LB + ch * 8) * 2);
                    cp16(d, bp + (long long)(bn + n) * ldb + k0 + ch * 8);
                }
            }
        }
        cp_commit();
    };

    const int nch = K / BK;          // >= 2 for all call sites
    load_stage(0, 0);
    load_stage(1, 1);

    for (int c = 0; c < nch; c++) {
        const int st = c % NSTG;
        if (c + 2 < nch) { load_stage(c + 2, (c + 2) % NSTG); cp_wait2(); }
        else if (c + 1 < nch) cp_wait1();
        else cp_wait0();
        __syncthreads();
#pragma unroll
        for (int ks = 0; ks < 2; ks++) {
            FragB bfr[2][2];
#pragma unroll
            for (int p = 0; p < 2; p++)
#pragma unroll
                for (int j = 0; j < 2; j++) {
                    const bf16* ptr = Bs + (st * 2 + p) * SZB +
                        (BCOL ? ((wn + j * 16) * LB + ks * 16) : (ks * 16 * LB + wn + j * 16));
                    wmma::load_matrix_sync(bfr[p][j], ptr, LB);
                }
#pragma unroll
            for (int i = 0; i < FM; i++) {
                FragA a0, a1;
                wmma::load_matrix_sync(a0, As + (st * 2 + 0) * SZA + ks * 16 * LA + wm + i * 16, LA);
                wmma::load_matrix_sync(a1, As + (st * 2 + 1) * SZA + ks * 16 * LA + wm + i * 16, LA);
#pragma unroll
                for (int j = 0; j < 2; j++) {
                    wmma::mma_sync(acc[i][j], a0, bfr[0][j], acc[i][j]);
                    wmma::mma_sync(acc[i][j], a0, bfr[1][j], acc[i][j]);
                    wmma::mma_sync(acc[i][j], a1, bfr[0][j], acc[i][j]);
                }
            }
        }
        __syncthreads();
    }

    // ---- staged epilogue (overlay pipeline smem) ----
#pragma unroll
    for (int i = 0; i < FM; i++)
#pragma unroll
        for (int j = 0; j < 2; j++)
            wmma::store_matrix_sync(&stg[(wm + i * 16) * LS + wn + j * 16], acc[i][j], LS, wmma::mem_row_major);
    __syncthreads();

    for (int t = tid; t < MT * NT / 4; t += 256) {
        int row = t / (NT / 4), c4 = (t % (NT / 4)) * 4;
        float4 v = *(float4*)&stg[row * LS + c4];
        v.x *= alpha; v.y *= alpha; v.z *= alpha; v.w *= alpha;
        if (BIAS == 1) {
            float bb = bias[(z & 7) * sBias + bm + row];
            v.x += bb; v.y += bb; v.z += bb; v.w += bb;
        } else if (BIAS == 2) {
            const float* bp = bias + (z & 7) * sBias + bn + c4;
            v.x += bp[0]; v.y += bp[1]; v.z += bp[2]; v.w += bp[3];
        }
        if (RELU) {
            v.x = fmaxf(v.x, 0.f); v.y = fmaxf(v.y, 0.f);
            v.z = fmaxf(v.z, 0.f); v.w = fmaxf(v.w, 0.f);
        }
        long long idx = zC + (long long)(bm + row) * ldc + bn + c4;
        if (EPI == 0) {
            *(float4*)&C[idx] = v;
        } else {
            union { uint2 u; bf16 h[4]; } p0, p1;
            split2(v.x, p0.h[0], p1.h[0]);
            split2(v.y, p0.h[1], p1.h[1]);
            split2(v.z, p0.h[2], p1.h[2]);
            split2(v.w, p0.h[3], p1.h[3]);
            *(uint2*)&C0[idx] = p0.u;
            *(uint2*)&C1[idx] = p1.u;
        }
    }
}

// ---------------- one fused weight split: all 8 tensors -> arena ----------------
__global__ __launch_bounds__(256)
void wsplit_all(const float* __restrict__ We, const float* __restrict__ Wq,
                const float* __restrict__ Wk, const float* __restrict__ Wv,
                const float* __restrict__ Wo, const float* __restrict__ W1,
                const float* __restrict__ W2, const float* __restrict__ Wd,
                bf16* __restrict__ o0, bf16* __restrict__ o1)
{
    long long i4 = (long long)blockIdx.x * 256 + threadIdx.x;
    if (i4 >= WT_TOTAL / 4) return;
    long long i = i4 * 4;
    const float* src; long long off;
    if      (i < 65536)   { src = We; off = i; }
    else if (i < 851968)  { src = Wq; off = i - 65536; }
    else if (i < 1638400) { src = Wk; off = i - 851968; }
    else if (i < 2424832) { src = Wv; off = i - 1638400; }
    else if (i < 3211264) { src = Wo; off = i - 2424832; }
    else if (i < 6356992) { src = W1; off = i - 3211264; }
    else if (i < 9502720) { src = W2; off = i - 6356992; }
    else                  { src = Wd; off = i - 9502720; }
    float4 v = *(const float4*)(src + off);
    union { uint2 u; bf16 h[4]; } p0, p1;
    split2(v.x, p0.h[0], p1.h[0]);
    split2(v.y, p0.h[1], p1.h[1]);
    split2(v.z, p0.h[2], p1.h[2]);
    split2(v.w, p0.h[3], p1.h[3]);
    *(uint2*)&o0[i] = p0.u;
    *(uint2*)&o1[i] = p1.u;
}

// ---------------- bcat for all layers: [l][bq | bk] ----------------
__global__ void bcat_all(const float* __restrict__ bq, const float* __restrict__ bk,
                         float* __restrict__ o)
{
    int i = blockIdx.x * 256 + threadIdx.x;          // 0 .. 3*1024-1
    if (i >= NLAYERS * 2 * DMODEL) return;
    int l = i >> 10, j = i & 1023;
    o[i] = (j < DMODEL) ? bq[l * DMODEL + j] : bk[l * DMODEL + j - DMODEL];
}

// ---------------- elementwise / reduction kernels ----------------
__global__ __launch_bounds__(256)
void xsplit_t(const float* __restrict__ x, bf16* __restrict__ o0, bf16* __restrict__ o1)
{
    __shared__ float t[32][33];
    int m0 = blockIdx.x * 32, f0 = blockIdx.y * 32;
    int tx = threadIdx.x & 31, ty = threadIdx.x >> 5;
#pragma unroll
    for (int i = 0; i < 4; i++)
        t[ty + 8 * i][tx] = x[(long long)(m0 + ty + 8 * i) * INPUT_DIM + f0 + tx];
    __syncthreads();
#pragma unroll
    for (int i = 0; i < 4; i++) {
        float v = t[tx][ty + 8 * i];
        long long idx = (long long)(f0 + ty + 8 * i) * ROWS + m0 + tx;
        bf16 s0, s1; split2(v, s0, s1);
        o0[idx] = s0; o1[idx] = s1;
    }
}

__global__ __launch_bounds__(256)
void pe_t(float* __restrict__ h, const float* __restrict__ bemb,
          bf16* __restrict__ o0, bf16* __restrict__ o1)
{
    int f = blockIdx.x;
    const float cc = 0.01798894603901634f;     // ln(10000)/512
    const float scale = 22.62741699796952f;    // sqrt(512)
    float div = __expf(-(float)(f & ~1) * cc);
    bool odd = f & 1;
    float bb = bemb[f];
    for (int m = threadIdx.x; m < ROWS; m += 256) {
        int pos = m & (SEQL - 1);
        float arg = (float)pos * div;
        float pe = odd ? cosf(arg) : sinf(arg);
        long long idx = (long long)f * ROWS + m;
        float v = (h[idx] + bb) * scale + pe;
        h[idx] = v;
        bf16 s0, s1; split2(v, s0, s1);
        o0[idx] = s0; o1[idx] = s1;
    }
}

// feature-major LN over features: block = 32 tokens
__global__ __launch_bounds__(256)
void add_ln_t(const float* __restrict__ resid, const float* __restrict__ delta,
              const float* __restrict__ dbias, float* __restrict__ out,
              bf16* __restrict__ o0, bf16* __restrict__ o1,
              const float* __restrict__ g, const float* __restrict__ b)
{
    __shared__ float S[8][32], S2[8][32], Sm[32], Sr[32];
    int m = blockIdx.x * 32 + (threadIdx.x & 31);
    int w = threadIdx.x >> 5;
    float s = 0.f, s2 = 0.f;
    for (int jj = 0; jj < 64; jj++) {
        int f = w * 64 + jj;
        float v = resid[(long long)f * ROWS + m] + delta[(long long)f * ROWS + m] + dbias[f];
        s += v; s2 += v * v;
    }
    S[w][threadIdx.x & 31] = s; S2[w][threadIdx.x & 31] = s2;
    __syncthreads();
    if (threadIdx.x < 32) {
        float a = 0.f, c = 0.f;
#pragma unroll
        for (int ww = 0; ww < 8; ww++) { a += S[ww][threadIdx.x]; c += S2[ww][threadIdx.x]; }
        float mean = a * (1.f / DMODEL);
        float var = c * (1.f / DMODEL) - mean * mean;
        Sm[threadIdx.x] = mean; Sr[threadIdx.x] = rsqrtf(var + 1e-5f);
    }
    __syncthreads();
    float mean = Sm[threadIdx.x & 31], rstd = Sr[threadIdx.x & 31];
    for (int jj = 0; jj < 64; jj++) {
        int f = w * 64 + jj;
        long long idx = (long long)f * ROWS + m;
        float v = resid[idx] + delta[idx] + dbias[f];
        float o = (v - mean) * rstd * g[f] + b[f];
        out[idx] = o;
        bf16 s0, s1; split2(o, s0, s1);
        o0[idx] = s0; o1[idx] = s1;
    }
}

// ---------------- exact top-u radix select + masked softmax -> P split2 ----------------
__global__ __launch_bounds__(256)
void topk_softmax_kernel(const float* __restrict__ scores,
                         bf16* __restrict__ P0, bf16* __restrict__ P1)
{
    __shared__ int hist[256];
    __shared__ float redf[256];
    __shared__ unsigned s_prefix;
    __shared__ int s_k;

    long long base = (long long)blockIdx.x * SEQL;
    int tid = threadIdx.x;
    float val[4];
    unsigned key[4];
#pragma unroll
    for (int i = 0; i < 4; i++) {
        val[i] = scores[base + tid + i * 256];
        unsigned bits = __float_as_uint(val[i]);
        key[i] = (bits & 0x80000000u) ? ~bits : (bits | 0x80000000u);
    }
    if (tid == 0) { s_prefix = 0u; s_k = TOPU; }
    __syncthreads();
    for (int shift = 24; shift >= 0; shift -= 8) {
        hist[tid] = 0;
        __syncthreads();
        unsigned pref = s_prefix;
        int k_cur = s_k;
#pragma unroll
        for (int i = 0; i < 4; i++) {
            bool active = (shift == 24) || ((key[i] >> (shift + 8)) == pref);
            if (active) atomicAdd(&hist[(key[i] >> shift) & 255u], 1);
        }
        __syncthreads();
        int own = hist[tid];
        for (int off = 1; off < 256; off <<= 1) {
            int other = (tid + off < 256) ? hist[tid + off] : 0;
            __syncthreads();
            hist[tid] += other;
            __syncthreads();
        }
        int suf = hist[tid];
        if (suf >= k_cur && suf - own < k_cur) {
            s_prefix = (pref << 8) | (unsigned)tid;
            s_k = k_cur - (suf - own);
        }
        __syncthreads();
    }
    unsigned tkey = s_prefix;
    unsigned tbits = (tkey & 0x80000000u) ? (tkey ^ 0x80000000u) : ~tkey;
    float thr = __uint_as_float(tbits);

    float m = -3.0e38f;
#pragma unroll
    for (int i = 0; i < 4; i++) if (val[i] >= thr) m = fmaxf(m, val[i]);
    redf[tid] = m;
    __syncthreads();
    for (int s = 128; s > 0; s >>= 1) { if (tid < s) redf[tid] = fmaxf(redf[tid], redf[tid + s]); __syncthreads(); }
    m = redf[0];
    __syncthreads();
    float e[4]; float sum = 0.f;
#pragma unroll
    for (int i = 0; i < 4; i++) {
        e[i] = (val[i] >= thr) ? __expf(val[i] - m) : 0.f;
        sum += e[i];
    }
    redf[tid] = sum;
    __syncthreads();
    for (int s = 128; s > 0; s >>= 1) { if (tid < s) redf[tid] += redf[tid + s]; __syncthreads(); }
    float inv = 1.f / redf[0];
#pragma unroll
    for (int i = 0; i < 4; i++) {
        float p = e[i] * inv;
        bf16 s0, s1; split2(p, s0, s1);
        P0[base + tid + i * 256] = s0;
        P1[base + tid + i * 256] = s1;
    }
}

// ---------------- host launch ----------------
extern "C" void kernel_launch(void* const* d_in, const int* in_sizes, int n_in,
                              void* d_out, int out_size)
{
    const float* x     = (const float*)d_in[0];
    const float* W_emb = (const float*)d_in[1];
    const float* b_emb = (const float*)d_in[2];
    const float* Wq    = (const float*)d_in[3];
    const float* bq    = (const float*)d_in[4];
    const float* Wk    = (const float*)d_in[5];
    const float* bk    = (const float*)d_in[6];
    const float* Wv    = (const float*)d_in[7];
    const float* bv    = (const float*)d_in[8];
    const float* Wo    = (const float*)d_in[9];
    const float* bo    = (const float*)d_in[10];
    const float* ln1_g = (const float*)d_in[11];
    const float* ln1_b = (const float*)d_in[12];
    const float* W1    = (const float*)d_in[13];
    const float* b1    = (const float*)d_in[14];
    const float* W2    = (const float*)d_in[15];
    const float* b2    = (const float*)d_in[16];
    const float* ln2_g = (const float*)d_in[17];
    const float* ln2_b = (const float*)d_in[18];
    const float* W_dec = (const float*)d_in[19];
    const float* b_dec = (const float*)d_in[20];
    float* out = (float*)d_out;

    float *h, *t2, *sc, *bcat;
    bf16 *x0, *x1, *h0, *h1, *qk0, *qk1, *v0, *v1, *a0, *a1, *f0, *f1, *P0, *P1, *w0, *w1;
    cudaGetSymbolAddress((void**)&h, g_h);
    cudaGetSymbolAddress((void**)&t2, g_t2);
    cudaGetSymbolAddress((void**)&sc, g_sc);
    cudaGetSymbolAddress((void**)&bcat, g_bcat);
    cudaGetSymbolAddress((void**)&x0, g_x0);  cudaGetSymbolAddress((void**)&x1, g_x1);
    cudaGetSymbolAddress((void**)&h0, g_h0);  cudaGetSymbolAddress((void**)&h1, g_h1);
    cudaGetSymbolAddress((void**)&qk0, g_qk0); cudaGetSymbolAddress((void**)&qk1, g_qk1);
    cudaGetSymbolAddress((void**)&v0, g_v0);  cudaGetSymbolAddress((void**)&v1, g_v1);
    cudaGetSymbolAddress((void**)&a0, g_a0);  cudaGetSymbolAddress((void**)&a1, g_a1);
    cudaGetSymbolAddress((void**)&f0, g_f0);  cudaGetSymbolAddress((void**)&f1, g_f1);
    cudaGetSymbolAddress((void**)&P0, g_P0);  cudaGetSymbolAddress((void**)&P1, g_P1);
    cudaGetSymbolAddress((void**)&w0, g_w0);  cudaGetSymbolAddress((void**)&w1, g_w1);

    // instantiations + smem (3-stage)
    auto k64f  = gk<64, 128, 0, 0, false, false>;   // emb / proj / FF2
    auto kQK   = gk<64, 128, 1, 1, false, false>;
    auto kV    = gk<64, 128, 2, 1, false, false>;
    auto kSc   = gk<128, 128, 0, 0, false, false>;
    auto kPV   = gk<64, 128, 0, 1, true,  false>;
    auto kFF1  = gk<128, 128, 1, 1, false, true>;
    auto kDec  = gk<128, 64, 2, 0, false, false>;
    const int SM64  = 79872;    // (3*2*(32*72) + 3*2*(32*136)) * 2
    const int SM128 = 104448;   // (3*2*(32*136) * 2) * 2
    const int SMPV  = 89088;    // (3*2*(32*72) + 3*2*(128*40)) * 2
    const int SMDEC = 79872;    // (3*2*(32*136) + 3*2*(32*72)) * 2
    cudaFuncSetAttribute(k64f, cudaFuncAttributeMaxDynamicSharedMemorySize, SM64);
    cudaFuncSetAttribute(kQK,  cudaFuncAttributeMaxDynamicSharedMemorySize, SM64);
    cudaFuncSetAttribute(kV,   cudaFuncAttributeMaxDynamicSharedMemorySize, SM64);
    cudaFuncSetAttribute(kSc,  cudaFuncAttributeMaxDynamicSharedMemorySize, SM128);
    cudaFuncSetAttribute(kPV,  cudaFuncAttributeMaxDynamicSharedMemorySize, SMPV);
    cudaFuncSetAttribute(kFF1, cudaFuncAttributeMaxDynamicSharedMemorySize, SM128);
    cudaFuncSetAttribute(kDec, cudaFuncAttributeMaxDynamicSharedMemorySize, SMDEC);

    // launches 0..4 (launch 5 = layer-0 kQK, which ncu -s 5 -c 1 profiles)
    wsplit_all<<<(int)((WT_TOTAL / 4 + 255) / 256), 256>>>(
        W_emb, Wq, Wk, Wv, Wo, W1, W2, W_dec, w0, w1);                     // 0
    xsplit_t<<<dim3(ROWS / 32, INPUT_DIM / 32), 256>>>(x, x0, x1);         // 1
    k64f<<<dim3(32, 8, 1), 256, SM64>>>(
        w0 + W_EMB, w1 + W_EMB, DMODEL, 0, 0,
        x0, x1, ROWS, 0, 0,
        h, nullptr, nullptr, ROWS, 0, 0,
        INPUT_DIM, nullptr, 0, 1.f);                                       // 2
    pe_t<<<DMODEL, 256>>>(h, b_emb, h0, h1);                               // 3
    bcat_all<<<(NLAYERS * 2 * DMODEL + 255) / 256, 256>>>(bq, bk, bcat);   // 4

    const long long QKOFF = (long long)DMODEL * ROWS;   // K plane offset in qk arena

    for (int l = 0; l < NLAYERS; l++) {
        // Q_t, K_t (fused; z=0 -> Q weights/bias, z=1 -> K)
        kQK<<<dim3(32, 8, 2), 256, SM64>>>(
            w0 + W_Qo(l), w1 + W_Qo(l), DMODEL, 0, W_Ko(l) - W_Qo(l),
            h0, h1, ROWS, 0, 0,
            nullptr, qk0, qk1, ROWS, 0, QKOFF,
            DMODEL, bcat + l * 2 * DMODEL, DMODEL, 1.f);
        // V (token-major out)
        kV<<<dim3(4, 64, 1), 256, SM64>>>(
            h0, h1, ROWS, 0, 0,
            w0 + W_Vo(l), w1 + W_Vo(l), DMODEL, 0, 0,
            nullptr, v0, v1, DMODEL, 0, 0,
            DMODEL, bv + l * DMODEL, 0, 1.f);
        // scores = (Q^T K) / 8 per (b,h)
        kSc<<<dim3(8, 8, BH), 256, SM128>>>(
            qk0, qk1, ROWS, SEQL, (long long)DK * ROWS,
            qk0 + QKOFF, qk1 + QKOFF, ROWS, SEQL, (long long)DK * ROWS,
            sc, nullptr, nullptr, SEQL, 8 * SB, SB,
            DK, nullptr, 0, 0.125f);
        topk_softmax_kernel<<<BH * SEQL, 256>>>(sc, P0, P1);
        // attn_t = V^T @ P^T  (B = P via col-major fragments)
        kPV<<<dim3(8, 1, BH), 256, SMPV>>>(
            v0, v1, DMODEL, (long long)SEQL * DMODEL, DK,
            P0, P1, SEQL, 8 * SB, SB,
            nullptr, a0, a1, ROWS, SEQL, (long long)DK * ROWS,
            SEQL, nullptr, 0, 1.f);
        // proj
        k64f<<<dim3(32, 8, 1), 256, SM64>>>(
            w0 + W_Oo(l), w1 + W_Oo(l), DMODEL, 0, 0,
            a0, a1, ROWS, 0, 0,
            t2, nullptr, nullptr, ROWS, 0, 0,
            DMODEL, nullptr, 0, 1.f);
        add_ln_t<<<ROWS / 32, 256>>>(h, t2, bo + l * DMODEL, h, h0, h1,
                                     ln1_g + l * DMODEL, ln1_b + l * DMODEL);
        // FF1 (bias row + relu + split)
        kFF1<<<dim3(32, 16, 1), 256, SM128>>>(
            w0 + W_1o(l), w1 + W_1o(l), DFF, 0, 0,
            h0, h1, ROWS, 0, 0,
            nullptr, f0, f1, ROWS, 0, 0,
            DMODEL, b1 + l * DFF, 0, 1.f);
        // FF2
        k64f<<<dim3(32, 8, 1), 256, SM64>>>(
            w0 + W_2o(l), w1 + W_2o(l), DMODEL, 0, 0,
            f0, f1, ROWS, 0, 0,
            t2, nullptr, nullptr, ROWS, 0, 0,
            DFF, nullptr, 0, 1.f);
        add_ln_t<<<ROWS / 32, 256>>>(h, t2, b2 + l * DMODEL, h, h0, h1,
                                     ln2_g + l * DMODEL, ln2_b + l * DMODEL);
    }

    // decoder: out[token][class]
    kDec<<<dim3(1, 32, 1), 256, SMDEC>>>(
        h0, h1, ROWS, 0, 0,
        w0 + W_DEC, w1 + W_DEC, NUM_CLASSES, 0, 0,
        out, nullptr, nullptr, NUM_CLASSES, 0, 0,
        DMODEL, b_dec, 0, 1.f);
}

// round 7
// speedup vs baseline: 3.0149x; 1.1119x over previous
#include <cuda_runtime.h>
#include <cuda_bf16.h>
#include <mma.h>
#include <cstdint>
#include <type_traits>
#include <math.h>
using namespace nvcuda;

#define BATCH 4
#define SEQL  1024
#define DMODEL 512
#define NHEAD 8
#define DK 64
#define NLAYERS 3
#define DFF 2048
#define INPUT_DIM 128
#define NUM_CLASSES 64
#define ROWS 4096
#define TOPU 34
#define BH 32
#define SB ((long long)SEQL*SEQL)
#define BK 32
#define NSTG 3
#define PSLOTS 128
typedef __nv_bfloat16 bf16;

// ---------------- scratch (static device globals) ----------------
__device__ __align__(16) float g_h [DMODEL*ROWS];     // h_t  [feature][token] fp32
__device__ __align__(16) float g_t2[DMODEL*ROWS];     // tmp2_t fp32
__device__ __align__(16) float g_sc[(long long)BH*SB];
__device__ __align__(16) float g_bcat[NLAYERS*2*DMODEL];
__device__ __align__(16) bf16 g_x0[INPUT_DIM*ROWS], g_x1[INPUT_DIM*ROWS];     // x_t planes
__device__ __align__(16) bf16 g_h0[DMODEL*ROWS],  g_h1[DMODEL*ROWS];          // h_t planes
__device__ __align__(16) bf16 g_qk0[2*DMODEL*ROWS], g_qk1[2*DMODEL*ROWS];     // Q_t then K_t
__device__ __align__(16) bf16 g_v0[ROWS*DMODEL],  g_v1[ROWS*DMODEL];          // V token-major
__device__ __align__(16) bf16 g_a0[ROWS*DMODEL],  g_a1[ROWS*DMODEL];          // attn token-major
__device__ __align__(16) bf16 g_f0[DFF*ROWS],     g_f1[DFF*ROWS];             // ff_t planes
// compact sparse P: per query row (BH*SEQL rows) up to PSLOTS entries
__device__ __align__(16) int   g_pidx[(long long)BH*SEQL*PSLOTS];
__device__ __align__(16) float g_pval[(long long)BH*SEQL*PSLOTS];
__device__ __align__(16) int   g_pcnt[BH*SEQL];

// weight arena: [emb][Q x3][K x3][V x3][O x3][W1 x3][W2 x3][dec]
#define W_EMB 0
#define W_Qo(l) (65536LL   + (long long)(l)*262144)
#define W_Ko(l) (851968LL  + (long long)(l)*262144)
#define W_Vo(l) (1638400LL + (long long)(l)*262144)
#define W_Oo(l) (2424832LL + (long long)(l)*262144)
#define W_1o(l) (3211264LL + (long long)(l)*1048576)
#define W_2o(l) (6356992LL + (long long)(l)*1048576)
#define W_DEC 9502720LL
#define WT_TOTAL 9535488LL
__device__ __align__(16) bf16 g_w0[WT_TOTAL], g_w1[WT_TOTAL];

// ---------------- helpers ----------------
__device__ __forceinline__ uint32_t smem_to_u32(const void* p) {
    uint32_t a;
    asm("{ .reg .u64 t; cvta.to.shared.u64 t, %1; cvt.u32.u64 %0, t; }" : "=r"(a) : "l"(p));
    return a;
}
__device__ __forceinline__ void cp16(uint32_t s, const bf16* g) {
    asm volatile("{ .reg .u64 p; cvta.to.global.u64 p, %1; cp.async.cg.shared.global [%0], [p], 16; }"
                 :: "r"(s), "l"(g) : "memory");
}
__device__ __forceinline__ void cp_commit() { asm volatile("cp.async.commit_group;" ::: "memory"); }
__device__ __forceinline__ void cp_wait2()  { asm volatile("cp.async.wait_group 2;" ::: "memory"); }
__device__ __forceinline__ void cp_wait1()  { asm volatile("cp.async.wait_group 1;" ::: "memory"); }
__device__ __forceinline__ void cp_wait0()  { asm volatile("cp.async.wait_group 0;" ::: "memory"); }

__device__ __forceinline__ void split2(float v, bf16& s0, bf16& s1) {
    s0 = __float2bfloat16_rn(v);
    s1 = __float2bfloat16_rn(v - __bfloat162float(s0));
}

// ---------------- bf16x2 tensor GEMM (3-stage cp.async pipeline) ----------------
// C[M][N] = alpha * sum_k (A0+A1)[k][m] * (B0+B1)[k][n]   (3 products)
// A global: [K][Mglob]. B: [K][Nglob] (BCOL=0) or [Nglob][K] (BCOL=1).
// BIAS: 0 none, 1 per-M-row, 2 per-N-col. EPI: 0 fp32 out, 1 split2 bf16 out.
template<int MT, int NT, int BIAS, int EPI, bool BCOL, bool RELU>
__global__ __launch_bounds__(256, 2)
void gk(const bf16* __restrict__ A0, const bf16* __restrict__ A1,
        int lda, long long sAo, long long sAi,
        const bf16* __restrict__ B0, const bf16* __restrict__ B1,
        int ldb, long long sBo, long long sBi,
        float* __restrict__ C, bf16* __restrict__ C0, bf16* __restrict__ C1,
        int ldc, long long sCo, long long sCi,
        int K, const float* __restrict__ bias, long long sBias, float alpha)
{
    extern __shared__ char smc[];
    constexpr int LA = MT + 8;
    constexpr int SZA = BK * LA;                         // elems, per plane-stage
    constexpr int LB = BCOL ? (BK + 8) : (NT + 8);
    constexpr int SZB = BCOL ? (NT * LB) : (BK * LB);
    constexpr int A_ELEMS = NSTG * 2 * SZA;              // stages x planes
    constexpr int LS = NT + 4;                           // staging ld (fp32)
    bf16* As = (bf16*)smc;
    bf16* Bs = As + A_ELEMS;
    float* stg = (float*)smc;

    const uint32_t smb = smem_to_u32(smc);
    const uint32_t smB = smb + A_ELEMS * 2;
    const int tid = threadIdx.x, wid = tid >> 5;
    const int z = blockIdx.z;
    const int bm = blockIdx.y * MT, bn = blockIdx.x * NT;
    const long long zA = (long long)(z >> 3) * sAo + (long long)(z & 7) * sAi;
    const long long zB = (long long)(z >> 3) * sBo + (long long)(z & 7) * sBi;
    const long long zC = (long long)(z >> 3) * sCo + (long long)(z & 7) * sCi;
    const bf16* Ap[2] = { A0 + zA, A1 + zA };
    const bf16* Bp[2] = { B0 + zB, B1 + zB };

    // warp tiling: WN_CNT warps across N (32 cols each), 8/WN_CNT groups across M
    constexpr int WN_CNT = NT / 32;
    constexpr int WM = MT * WN_CNT / 8;
    constexpr int FM = WM / 16;
    const int wm = (wid / WN_CNT) * WM;
    const int wn = (wid % WN_CNT) * 32;

    using FragA = wmma::fragment<wmma::matrix_a, 16, 16, 16, bf16, wmma::col_major>;
    using BLay  = typename std::conditional<BCOL, wmma::col_major, wmma::row_major>::type;
    using FragB = wmma::fragment<wmma::matrix_b, 16, 16, 16, bf16, BLay>;
    wmma::fragment<wmma::accumulator, 16, 16, 16, float> acc[FM][2];
#pragma unroll
    for (int i = 0; i < FM; i++)
#pragma unroll
        for (int j = 0; j < 2; j++) wmma::fill_fragment(acc[i][j], 0.f);

    auto load_stage = [&](int c, int st) {
        const int k0 = c * BK;
#pragma unroll
        for (int p = 0; p < 2; p++) {
            const bf16* ap = Ap[p];
            for (int t = tid; t < 4 * MT; t += 256) {
                int k = t / (MT / 8), ch = t % (MT / 8);
                uint32_t d = smb + (uint32_t)(((st * 2 + p) * SZA + k * LA + ch * 8) * 2);
                cp16(d, ap + (long long)(k0 + k) * lda + bm + ch * 8);
            }
            const bf16* bp = Bp[p];
            if (!BCOL) {
                for (int t = tid; t < 4 * NT; t += 256) {
                    int k = t / (NT / 8), ch = t % (NT / 8);
                    uint32_t d = smB + (uint32_t)(((st * 2 + p) * SZB + k * LB + ch * 8) * 2);
                    cp16(d, bp + (long long)(k0 + k) * ldb + bn + ch * 8);
                }
            } else {
                for (int t = tid; t < 4 * NT; t += 256) {
                    int n = t >> 2, ch = t & 3;
                    uint32_t d = smB + (uint32_t)(((st * 2 + p) * SZB + n * LB + ch * 8) * 2);
                    cp16(d, bp + (long long)(bn + n) * ldb + k0 + ch * 8);
                }
            }
        }
        cp_commit();
    };

    const int nch = K / BK;          // >= 2 for all call sites
    load_stage(0, 0);
    load_stage(1, 1);

    for (int c = 0; c < nch; c++) {
        const int st = c % NSTG;
        if (c + 2 < nch) { load_stage(c + 2, (c + 2) % NSTG); cp_wait2(); }
        else if (c + 1 < nch) cp_wait1();
        else cp_wait0();
        __syncthreads();
#pragma unroll
        for (int ks = 0; ks < 2; ks++) {
            FragB bfr[2][2];
#pragma unroll
            for (int p = 0; p < 2; p++)
#pragma unroll
                for (int j = 0; j < 2; j++) {
                    const bf16* ptr = Bs + (st * 2 + p) * SZB +
                        (BCOL ? ((wn + j * 16) * LB + ks * 16) : (ks * 16 * LB + wn + j * 16));
                    wmma::load_matrix_sync(bfr[p][j], ptr, LB);
                }
#pragma unroll
            for (int i = 0; i < FM; i++) {
                FragA a0, a1;
                wmma::load_matrix_sync(a0, As + (st * 2 + 0) * SZA + ks * 16 * LA + wm + i * 16, LA);
                wmma::load_matrix_sync(a1, As + (st * 2 + 1) * SZA + ks * 16 * LA + wm + i * 16, LA);
#pragma unroll
                for (int j = 0; j < 2; j++) {
                    wmma::mma_sync(acc[i][j], a0, bfr[0][j], acc[i][j]);
                    wmma::mma_sync(acc[i][j], a0, bfr[1][j], acc[i][j]);
                    wmma::mma_sync(acc[i][j], a1, bfr[0][j], acc[i][j]);
                }
            }
        }
        __syncthreads();
    }

    // ---- staged epilogue (overlay pipeline smem) ----
#pragma unroll
    for (int i = 0; i < FM; i++)
#pragma unroll
        for (int j = 0; j < 2; j++)
            wmma::store_matrix_sync(&stg[(wm + i * 16) * LS + wn + j * 16], acc[i][j], LS, wmma::mem_row_major);
    __syncthreads();

    for (int t = tid; t < MT * NT / 4; t += 256) {
        int row = t / (NT / 4), c4 = (t % (NT / 4)) * 4;
        float4 v = *(float4*)&stg[row * LS + c4];
        v.x *= alpha; v.y *= alpha; v.z *= alpha; v.w *= alpha;
        if (BIAS == 1) {
            float bb = bias[(z & 7) * sBias + bm + row];
            v.x += bb; v.y += bb; v.z += bb; v.w += bb;
        } else if (BIAS == 2) {
            const float* bp = bias + (z & 7) * sBias + bn + c4;
            v.x += bp[0]; v.y += bp[1]; v.z += bp[2]; v.w += bp[3];
        }
        if (RELU) {
            v.x = fmaxf(v.x, 0.f); v.y = fmaxf(v.y, 0.f);
            v.z = fmaxf(v.z, 0.f); v.w = fmaxf(v.w, 0.f);
        }
        long long idx = zC + (long long)(bm + row) * ldc + bn + c4;
        if (EPI == 0) {
            *(float4*)&C[idx] = v;
        } else {
            union { uint2 u; bf16 h[4]; } p0, p1;
            split2(v.x, p0.h[0], p1.h[0]);
            split2(v.y, p0.h[1], p1.h[1]);
            split2(v.z, p0.h[2], p1.h[2]);
            split2(v.w, p0.h[3], p1.h[3]);
            *(uint2*)&C0[idx] = p0.u;
            *(uint2*)&C1[idx] = p1.u;
        }
    }
}

// ---------------- one fused weight split: all 8 tensors -> arena ----------------
__global__ __launch_bounds__(256)
void wsplit_all(const float* __restrict__ We, const float* __restrict__ Wq,
                const float* __restrict__ Wk, const float* __restrict__ Wv,
                const float* __restrict__ Wo, const float* __restrict__ W1,
                const float* __restrict__ W2, const float* __restrict__ Wd,
                bf16* __restrict__ o0, bf16* __restrict__ o1)
{
    long long i4 = (long long)blockIdx.x * 256 + threadIdx.x;
    if (i4 >= WT_TOTAL / 4) return;
    long long i = i4 * 4;
    const float* src; long long off;
    if      (i < 65536)   { src = We; off = i; }
    else if (i < 851968)  { src = Wq; off = i - 65536; }
    else if (i < 1638400) { src = Wk; off = i - 851968; }
    else if (i < 2424832) { src = Wv; off = i - 1638400; }
    else if (i < 3211264) { src = Wo; off = i - 2424832; }
    else if (i < 6356992) { src = W1; off = i - 3211264; }
    else if (i < 9502720) { src = W2; off = i - 6356992; }
    else                  { src = Wd; off = i - 9502720; }
    float4 v = *(const float4*)(src + off);
    union { uint2 u; bf16 h[4]; } p0, p1;
    split2(v.x, p0.h[0], p1.h[0]);
    split2(v.y, p0.h[1], p1.h[1]);
    split2(v.z, p0.h[2], p1.h[2]);
    split2(v.w, p0.h[3], p1.h[3]);
    *(uint2*)&o0[i] = p0.u;
    *(uint2*)&o1[i] = p1.u;
}

// ---------------- bcat for all layers: [l][bq | bk] ----------------
__global__ void bcat_all(const float* __restrict__ bq, const float* __restrict__ bk,
                         float* __restrict__ o)
{
    int i = blockIdx.x * 256 + threadIdx.x;          // 0 .. 3*1024-1
    if (i >= NLAYERS * 2 * DMODEL) return;
    int l = i >> 10, j = i & 1023;
    o[i] = (j < DMODEL) ? bq[l * DMODEL + j] : bk[l * DMODEL + j - DMODEL];
}

// ---------------- elementwise / reduction kernels ----------------
__global__ __launch_bounds__(256)
void xsplit_t(const float* __restrict__ x, bf16* __restrict__ o0, bf16* __restrict__ o1)
{
    __shared__ float t[32][33];
    int m0 = blockIdx.x * 32, f0 = blockIdx.y * 32;
    int tx = threadIdx.x & 31, ty = threadIdx.x >> 5;
#pragma unroll
    for (int i = 0; i < 4; i++)
        t[ty + 8 * i][tx] = x[(long long)(m0 + ty + 8 * i) * INPUT_DIM + f0 + tx];
    __syncthreads();
#pragma unroll
    for (int i = 0; i < 4; i++) {
        float v = t[tx][ty + 8 * i];
        long long idx = (long long)(f0 + ty + 8 * i) * ROWS + m0 + tx;
        bf16 s0, s1; split2(v, s0, s1);
        o0[idx] = s0; o1[idx] = s1;
    }
}

__global__ __launch_bounds__(256)
void pe_t(float* __restrict__ h, const float* __restrict__ bemb,
          bf16* __restrict__ o0, bf16* __restrict__ o1)
{
    int f = blockIdx.x;
    const float cc = 0.01798894603901634f;     // ln(10000)/512
    const float scale = 22.62741699796952f;    // sqrt(512)
    float div = __expf(-(float)(f & ~1) * cc);
    bool odd = f & 1;
    float bb = bemb[f];
    for (int m = threadIdx.x; m < ROWS; m += 256) {
        int pos = m & (SEQL - 1);
        float arg = (float)pos * div;
        float pe = odd ? cosf(arg) : sinf(arg);
        long long idx = (long long)f * ROWS + m;
        float v = (h[idx] + bb) * scale + pe;
        h[idx] = v;
        bf16 s0, s1; split2(v, s0, s1);
        o0[idx] = s0; o1[idx] = s1;
    }
}

// feature-major LN over features: block = 32 tokens
__global__ __launch_bounds__(256)
void add_ln_t(const float* __restrict__ resid, const float* __restrict__ delta,
              const float* __restrict__ dbias, float* __restrict__ out,
              bf16* __restrict__ o0, bf16* __restrict__ o1,
              const float* __restrict__ g, const float* __restrict__ b)
{
    __shared__ float S[8][32], S2[8][32], Sm[32], Sr[32];
    int m = blockIdx.x * 32 + (threadIdx.x & 31);
    int w = threadIdx.x >> 5;
    float s = 0.f, s2 = 0.f;
    for (int jj = 0; jj < 64; jj++) {
        int f = w * 64 + jj;
        float v = resid[(long long)f * ROWS + m] + delta[(long long)f * ROWS + m] + dbias[f];
        s += v; s2 += v * v;
    }
    S[w][threadIdx.x & 31] = s; S2[w][threadIdx.x & 31] = s2;
    __syncthreads();
    if (threadIdx.x < 32) {
        float a = 0.f, c = 0.f;
#pragma unroll
        for (int ww = 0; ww < 8; ww++) { a += S[ww][threadIdx.x]; c += S2[ww][threadIdx.x]; }
        float mean = a * (1.f / DMODEL);
        float var = c * (1.f / DMODEL) - mean * mean;
        Sm[threadIdx.x] = mean; Sr[threadIdx.x] = rsqrtf(var + 1e-5f);
    }
    __syncthreads();
    float mean = Sm[threadIdx.x & 31], rstd = Sr[threadIdx.x & 31];
    for (int jj = 0; jj < 64; jj++) {
        int f = w * 64 + jj;
        long long idx = (long long)f * ROWS + m;
        float v = resid[idx] + delta[idx] + dbias[f];
        float o = (v - mean) * rstd * g[f] + b[f];
        out[idx] = o;
        bf16 s0, s1; split2(o, s0, s1);
        o0[idx] = s0; o1[idx] = s1;
    }
}

// ---------------- exact top-u radix select + masked softmax -> compact sparse P ----------------
__global__ __launch_bounds__(256)
void topk_compact(const float* __restrict__ scores,
                  int* __restrict__ pcnt, int* __restrict__ pidx, float* __restrict__ pval)
{
    __shared__ int hist[256];
    __shared__ int wtot[8], wsufex[8];
    __shared__ float wredA[8], wredB[8];
    __shared__ unsigned s_prefix;
    __shared__ int s_k, scnt;

    long long base = (long long)blockIdx.x * SEQL;
    long long prow = (long long)blockIdx.x * PSLOTS;
    int tid = threadIdx.x, lane = tid & 31, w = tid >> 5;
    float val[4];
    unsigned key[4];
#pragma unroll
    for (int i = 0; i < 4; i++) {
        val[i] = scores[base + tid + i * 256];
        unsigned bits = __float_as_uint(val[i]);
        key[i] = (bits & 0x80000000u) ? ~bits : (bits | 0x80000000u);
    }
    if (tid == 0) { s_prefix = 0u; s_k = TOPU; scnt = 0; }
    __syncthreads();

    for (int shift = 24; shift >= 0; shift -= 8) {
        hist[tid] = 0;
        __syncthreads();
        unsigned pref = s_prefix;
        int k_cur = s_k;
#pragma unroll
        for (int i = 0; i < 4; i++) {
            bool active = (shift == 24) || ((key[i] >> (shift + 8)) == pref);
            if (active) atomicAdd(&hist[(key[i] >> shift) & 255u], 1);
        }
        __syncthreads();
        int own = hist[tid];
        // warp-level inclusive suffix sum over this warp's 32 bins
        int ssum = own;
#pragma unroll
        for (int off = 1; off < 32; off <<= 1) {
            int o = __shfl_down_sync(0xffffffffu, ssum, off);
            if (lane + off < 32) ssum += o;
        }
        if (lane == 0) wtot[w] = ssum;      // lane0 suffix = warp total
        __syncthreads();
        if (tid < 8) {
            int e = 0;
            for (int j = tid + 1; j < 8; j++) e += wtot[j];
            wsufex[tid] = e;
        }
        __syncthreads();
        int suf = ssum + wsufex[w];         // count of elements with digit >= tid
        if (suf >= k_cur && suf - own < k_cur) {
            s_prefix = (pref << 8) | (unsigned)tid;
            s_k = k_cur - (suf - own);
        }
        __syncthreads();
    }
    unsigned tkey = s_prefix;
    unsigned tbits = (tkey & 0x80000000u) ? (tkey ^ 0x80000000u) : ~tkey;
    float thr = __uint_as_float(tbits);

    // max (masked) via shfl
    float m = -3.0e38f;
#pragma unroll
    for (int i = 0; i < 4; i++) if (val[i] >= thr) m = fmaxf(m, val[i]);
#pragma unroll
    for (int off = 16; off > 0; off >>= 1) m = fmaxf(m, __shfl_xor_sync(0xffffffffu, m, off));
    if (lane == 0) wredA[w] = m;
    __syncthreads();
    if (w == 0) {
        float t = (lane < 8) ? wredA[lane] : -3.0e38f;
#pragma unroll
        for (int off = 4; off > 0; off >>= 1) t = fmaxf(t, __shfl_xor_sync(0xffffffffu, t, off));
        if (lane == 0) wredA[0] = t;
    }
    __syncthreads();
    m = wredA[0];

    float e[4]; float sum = 0.f;
#pragma unroll
    for (int i = 0; i < 4; i++) {
        e[i] = (val[i] >= thr) ? __expf(val[i] - m) : 0.f;
        sum += e[i];
    }
#pragma unroll
    for (int off = 16; off > 0; off >>= 1) sum += __shfl_xor_sync(0xffffffffu, sum, off);
    if (lane == 0) wredB[w] = sum;
    __syncthreads();
    if (w == 0) {
        float t = (lane < 8) ? wredB[lane] : 0.f;
#pragma unroll
        for (int off = 4; off > 0; off >>= 1) t += __shfl_xor_sync(0xffffffffu, t, off);
        if (lane == 0) wredB[0] = t;
    }
    __syncthreads();
    float inv = 1.f / wredB[0];

    // compact write: (col, prob) for kept entries
#pragma unroll
    for (int i = 0; i < 4; i++) {
        if (val[i] >= thr) {
            int pos = atomicAdd(&scnt, 1);
            if (pos < PSLOTS) {
                pidx[prow + pos] = tid + i * 256;
                pval[prow + pos] = e[i] * inv;
            }
        }
    }
    __syncthreads();
    if (tid == 0) pcnt[blockIdx.x] = min(scnt, PSLOTS);
}

// ---------------- sparse PV gather: attn[token][feature] = sum_j p_j * V[j][feature] ----------------
// one warp per query token; lane covers dims 2*lane, 2*lane+1 of this head's 64
__global__ __launch_bounds__(256)
void pv_sparse(const int* __restrict__ pcnt, const int* __restrict__ pidx,
               const float* __restrict__ pval,
               const bf16* __restrict__ v0, const bf16* __restrict__ v1,
               bf16* __restrict__ a0, bf16* __restrict__ a1)
{
    int warpg = blockIdx.x * 8 + (threadIdx.x >> 5);   // query row id: bh*1024 + s
    int lane = threadIdx.x & 31;
    int bh = warpg >> 10, s = warpg & 1023;
    int b = bh >> 3, h = bh & 7;
    long long prow = (long long)warpg * PSLOTS;
    int cnt = pcnt[warpg];
    float accx = 0.f, accy = 0.f;

    for (int j0 = 0; j0 < cnt; j0 += 32) {
        int myj = j0 + lane;
        int t = 0; float p = 0.f;
        if (myj < cnt) { t = pidx[prow + myj]; p = pval[prow + myj]; }
        int lim = min(32, cnt - j0);
        for (int jj = 0; jj < lim; jj++) {
            int tt = __shfl_sync(0xffffffffu, t, jj);
            float pp = __shfl_sync(0xffffffffu, p, jj);
            long long vb = ((long long)(b * SEQL + tt)) * DMODEL + h * DK + lane * 2;
            uint32_t u0 = *(const uint32_t*)(v0 + vb);
            uint32_t u1 = *(const uint32_t*)(v1 + vb);
            __nv_bfloat162 h0 = *reinterpret_cast<__nv_bfloat162*>(&u0);
            __nv_bfloat162 h1 = *reinterpret_cast<__nv_bfloat162*>(&u1);
            float lo = __bfloat162float(h0.x) + __bfloat162float(h1.x);
            float hi = __bfloat162float(h0.y) + __bfloat162float(h1.y);
            accx = fmaf(pp, lo, accx);
            accy = fmaf(pp, hi, accy);
        }
    }
    long long ob = ((long long)(b * SEQL + s)) * DMODEL + h * DK + lane * 2;
    bf16 x0, x1, y0, y1;
    split2(accx, x0, x1);
    split2(accy, y0, y1);
    union { uint32_t u; bf16 hh[2]; } p0, p1;
    p0.hh[0] = x0; p0.hh[1] = y0;
    p1.hh[0] = x1; p1.hh[1] = y1;
    *(uint32_t*)(a0 + ob) = p0.u;
    *(uint32_t*)(a1 + ob) = p1.u;
}

// ---------------- host launch ----------------
extern "C" void kernel_launch(void* const* d_in, const int* in_sizes, int n_in,
                              void* d_out, int out_size)
{
    const float* x     = (const float*)d_in[0];
    const float* W_emb = (const float*)d_in[1];
    const float* b_emb = (const float*)d_in[2];
    const float* Wq    = (const float*)d_in[3];
    const float* bq    = (const float*)d_in[4];
    const float* Wk    = (const float*)d_in[5];
    const float* bk    = (const float*)d_in[6];
    const float* Wv    = (const float*)d_in[7];
    const float* bv    = (const float*)d_in[8];
    const float* Wo    = (const float*)d_in[9];
    const float* bo    = (const float*)d_in[10];
    const float* ln1_g = (const float*)d_in[11];
    const float* ln1_b = (const float*)d_in[12];
    const float* W1    = (const float*)d_in[13];
    const float* b1    = (const float*)d_in[14];
    const float* W2    = (const float*)d_in[15];
    const float* b2    = (const float*)d_in[16];
    const float* ln2_g = (const float*)d_in[17];
    const float* ln2_b = (const float*)d_in[18];
    const float* W_dec = (const float*)d_in[19];
    const float* b_dec = (const float*)d_in[20];
    float* out = (float*)d_out;

    float *h, *t2, *sc, *bcat, *pval;
    int *pidx, *pcnt;
    bf16 *x0, *x1, *h0, *h1, *qk0, *qk1, *v0, *v1, *a0, *a1, *f0, *f1, *w0, *w1;
    cudaGetSymbolAddress((void**)&h, g_h);
    cudaGetSymbolAddress((void**)&t2, g_t2);
    cudaGetSymbolAddress((void**)&sc, g_sc);
    cudaGetSymbolAddress((void**)&bcat, g_bcat);
    cudaGetSymbolAddress((void**)&x0, g_x0);  cudaGetSymbolAddress((void**)&x1, g_x1);
    cudaGetSymbolAddress((void**)&h0, g_h0);  cudaGetSymbolAddress((void**)&h1, g_h1);
    cudaGetSymbolAddress((void**)&qk0, g_qk0); cudaGetSymbolAddress((void**)&qk1, g_qk1);
    cudaGetSymbolAddress((void**)&v0, g_v0);  cudaGetSymbolAddress((void**)&v1, g_v1);
    cudaGetSymbolAddress((void**)&a0, g_a0);  cudaGetSymbolAddress((void**)&a1, g_a1);
    cudaGetSymbolAddress((void**)&f0, g_f0);  cudaGetSymbolAddress((void**)&f1, g_f1);
    cudaGetSymbolAddress((void**)&pidx, g_pidx);
    cudaGetSymbolAddress((void**)&pval, g_pval);
    cudaGetSymbolAddress((void**)&pcnt, g_pcnt);
    cudaGetSymbolAddress((void**)&w0, g_w0);  cudaGetSymbolAddress((void**)&w1, g_w1);

    // instantiations + smem (3-stage, BK=32)
    auto k128f = gk<128, 128, 0, 0, false, false>;  // emb / FF2 / scores
    auto kPRJ  = gk<128, 128, 0, 0, true,  false>;  // proj (B = token-major attn)
    auto kQK   = gk<128, 128, 1, 1, false, false>;
    auto kV    = gk<128, 128, 2, 1, false, false>;
    auto kFF1  = gk<128, 128, 1, 1, false, true>;
    auto kDec  = gk<128, 64, 2, 0, false, false>;
    const int SM128 = 104448;   // 2 * (3*2*(32*136)) * 2 bytes
    const int SMPRJ = 113664;   // A 52224 + BCOL B 61440
    const int SMDEC = 79872;
    cudaFuncSetAttribute(k128f, cudaFuncAttributeMaxDynamicSharedMemorySize, SM128);
    cudaFuncSetAttribute(kPRJ,  cudaFuncAttributeMaxDynamicSharedMemorySize, SMPRJ);
    cudaFuncSetAttribute(kQK,   cudaFuncAttributeMaxDynamicSharedMemorySize, SM128);
    cudaFuncSetAttribute(kV,    cudaFuncAttributeMaxDynamicSharedMemorySize, SM128);
    cudaFuncSetAttribute(kFF1,  cudaFuncAttributeMaxDynamicSharedMemorySize, SM128);
    cudaFuncSetAttribute(kDec,  cudaFuncAttributeMaxDynamicSharedMemorySize, SMDEC);

    wsplit_all<<<(int)((WT_TOTAL / 4 + 255) / 256), 256>>>(
        W_emb, Wq, Wk, Wv, Wo, W1, W2, W_dec, w0, w1);
    xsplit_t<<<dim3(ROWS / 32, INPUT_DIM / 32), 256>>>(x, x0, x1);
    k128f<<<dim3(32, 4, 1), 256, SM128>>>(
        w0 + W_EMB, w1 + W_EMB, DMODEL, 0, 0,
        x0, x1, ROWS, 0, 0,
        h, nullptr, nullptr, ROWS, 0, 0,
        INPUT_DIM, nullptr, 0, 1.f);
    pe_t<<<DMODEL, 256>>>(h, b_emb, h0, h1);
    bcat_all<<<(NLAYERS * 2 * DMODEL + 255) / 256, 256>>>(bq, bk, bcat);

    const long long QKOFF = (long long)DMODEL * ROWS;   // K plane offset in qk arena

    for (int l = 0; l < NLAYERS; l++) {
        // Q_t, K_t (fused; z=0 -> Q weights/bias, z=1 -> K)
        kQK<<<dim3(32, 4, 2), 256, SM128>>>(
            w0 + W_Qo(l), w1 + W_Qo(l), DMODEL, 0, W_Ko(l) - W_Qo(l),
            h0, h1, ROWS, 0, 0,
            nullptr, qk0, qk1, ROWS, 0, QKOFF,
            DMODEL, bcat + l * 2 * DMODEL, DMODEL, 1.f);
        // V (token-major out)
        kV<<<dim3(4, 32, 1), 256, SM128>>>(
            h0, h1, ROWS, 0, 0,
            w0 + W_Vo(l), w1 + W_Vo(l), DMODEL, 0, 0,
            nullptr, v0, v1, DMODEL, 0, 0,
            DMODEL, bv + l * DMODEL, 0, 1.f);
        // scores = (Q^T K) / 8 per (b,h)
        k128f<<<dim3(8, 8, BH), 256, SM128>>>(
            qk0, qk1, ROWS, SEQL, (long long)DK * ROWS,
            qk0 + QKOFF, qk1 + QKOFF, ROWS, SEQL, (long long)DK * ROWS,
            sc, nullptr, nullptr, SEQL, 8 * SB, SB,
            DK, nullptr, 0, 0.125f);
        // exact top-u + softmax -> compact sparse P
        topk_compact<<<BH * SEQL, 256>>>(sc, pcnt, pidx, pval);
        // sparse PV gather -> attn token-major
        pv_sparse<<<BH * SEQL / 8, 256>>>(pcnt, pidx, pval, v0, v1, a0, a1);
        // proj (B = token-major attn via BCOL)
        kPRJ<<<dim3(32, 4, 1), 256, SMPRJ>>>(
            w0 + W_Oo(l), w1 + W_Oo(l), DMODEL, 0, 0,
            a0, a1, DMODEL, 0, 0,
            t2, nullptr, nullptr, ROWS, 0, 0,
            DMODEL, nullptr, 0, 1.f);
        add_ln_t<<<ROWS / 32, 256>>>(h, t2, bo + l * DMODEL, h, h0, h1,
                                     ln1_g + l * DMODEL, ln1_b + l * DMODEL);
        // FF1 (bias row + relu + split)
        kFF1<<<dim3(32, 16, 1), 256, SM128>>>(
            w0 + W_1o(l), w1 + W_1o(l), DFF, 0, 0,
            h0, h1, ROWS, 0, 0,
            nullptr, f0, f1, ROWS, 0, 0,
            DMODEL, b1 + l * DFF, 0, 1.f);
        // FF2
        k128f<<<dim3(32, 4, 1), 256, SM128>>>(
            w0 + W_2o(l), w1 + W_2o(l), DMODEL, 0, 0,
            f0, f1, ROWS, 0, 0,
            t2, nullptr, nullptr, ROWS, 0, 0,
            DFF, nullptr, 0, 1.f);
        add_ln_t<<<ROWS / 32, 256>>>(h, t2, b2 + l * DMODEL, h, h0, h1,
                                     ln2_g + l * DMODEL, ln2_b + l * DMODEL);
    }

    // decoder: out[token][class]
    kDec<<<dim3(1, 32, 1), 256, SMDEC>>>(
        h0, h1, ROWS, 0, 0,
        w0 + W_DEC, w1 + W_DEC, NUM_CLASSES, 0, 0,
        out, nullptr, nullptr, NUM_CLASSES, 0, 0,
        DMODEL, b_dec, 0, 1.f);
}